// round 6
// baseline (speedup 1.0000x reference)
#include <cuda_runtime.h>
#include <cuda_fp16.h>
#include <cstdint>

// Problem constants
#define Bn 8
#define Sn 16
#define En 128
#define TOK (Bn*Sn*32*32)      // 131072
#define Pn (Bn*32*32)          // 8192
#define OC 512

// -------- scratch (device globals) --------
__device__ float g_projf[(long)TOK*128];
__device__ float g_qkv[(long)TOK*384];
__device__ float g_ccx[(long)TOK*OC];
__device__ float g_c[Pn*En];
__device__ __half g_xin2[(long)TOK*256];
__device__ __half g_xs2[(long)TOK*256];
__device__ __half g_ao[(long)TOK*256];
__device__ __half g_xp[(long)TOK*128];
__device__ __half g_hpp[2][Pn*128];           // ping-pong h
__device__ __half g_bx[(long)OC*1152];
__device__ __half g_bh[(long)OC*1152];
__device__ __half g_bproj[128*256];
__device__ __half g_bqkv[384*256];
__device__ __half g_bout[128*256];
// chain sync state
__device__ int g_cnt[64];
__device__ int g_barcnt;
__device__ volatile int g_sense;

// ==================== helpers ====================
__device__ __forceinline__ uint32_t smem_u32(const void* p) {
    uint32_t a;
    asm("{ .reg .u64 t; cvta.to.shared.u64 t, %1; cvt.u32.u64 %0, t; }" : "=r"(a) : "l"(p));
    return a;
}
__device__ __forceinline__ void cp16(uint32_t dst, const void* src, bool pred) {
    asm volatile("cp.async.cg.shared.global [%0], [%1], 16, %2;"
        :: "r"(dst), "l"(src), "r"(pred ? 16u : 0u));
}
#define CP_COMMIT() asm volatile("cp.async.commit_group;" ::: "memory")
#define CP_WAIT3()  asm volatile("cp.async.wait_group 3;" ::: "memory")
#define CP_WAIT2()  asm volatile("cp.async.wait_group 2;" ::: "memory")

__device__ __forceinline__ void ldm_x4(uint32_t* r, uint32_t addr) {
    asm volatile("ldmatrix.sync.aligned.m8n8.x4.shared.b16 {%0,%1,%2,%3}, [%4];"
        : "=r"(r[0]), "=r"(r[1]), "=r"(r[2]), "=r"(r[3]) : "r"(addr));
}
__device__ __forceinline__ void mma16816(float* d, const uint32_t* a, uint32_t b0, uint32_t b1) {
    asm volatile("mma.sync.aligned.m16n8k16.row.col.f32.f16.f16.f32 "
        "{%0,%1,%2,%3}, {%4,%5,%6,%7}, {%8,%9}, {%0,%1,%2,%3};"
        : "+f"(d[0]), "+f"(d[1]), "+f"(d[2]), "+f"(d[3])
        : "r"(a[0]), "r"(a[1]), "r"(a[2]), "r"(a[3]), "r"(b0), "r"(b1));
}
__device__ __forceinline__ void split_h(float x, __half& hi, __half& lo) {
    hi = __float2half(x);
    lo = __float2half(x - __half2float(hi));
}

// -------------------- small kernels --------------------
__global__ void zero_kernel(float* p, int n) {
    int i = blockIdx.x*blockDim.x + threadIdx.x;
    if (i < n) p[i] = 0.f;
    if (blockIdx.x == 0 && threadIdx.x < 64) g_cnt[threadIdx.x] = 0;
    if (blockIdx.x == 0 && threadIdx.x == 64) { g_barcnt = 0; g_sense = 0; }
}
__global__ void split_in(const float* __restrict__ inp, __half* __restrict__ x2) {
    long idx = (long)blockIdx.x*blockDim.x + threadIdx.x;
    if (idx >= (long)TOK*128) return;
    long row = idx >> 7; int e = idx & 127;
    __half hi, lo;
    split_h(inp[idx], hi, lo);
    x2[row*256 + e]       = hi;
    x2[row*256 + 128 + e] = lo;
}
__global__ void reorder_conv(const float* __restrict__ ck,
                             __half* __restrict__ bx, __half* __restrict__ bh) {
    long idx = (long)blockIdx.x*blockDim.x + threadIdx.x;
    if (idx >= (long)OC*1152) return;
    int oc = idx / 1152, k = idx % 1152;
    int tap = k >> 7, ic = k & 127;
    int ky = tap / 3, kx = tap % 3;
    bx[idx] = __float2half(ck[(((long)oc*256 + ic      )*3 + ky)*3 + kx]);
    bh[idx] = __float2half(ck[(((long)oc*256 + 128 + ic)*3 + ky)*3 + kx]);
}
template<int N>
__global__ void reorder_w2(const float* __restrict__ w, __half* __restrict__ b) {
    int idx = blockIdx.x*blockDim.x + threadIdx.x;
    if (idx >= N*128) return;
    int n = idx >> 7, k = idx & 127;
    __half v = __float2half(w[k*N + n]);
    b[n*256 + k]       = v;
    b[n*256 + 128 + k] = v;
}

// -------------------- silu + LN --------------------
__global__ __launch_bounds__(128)
void siluln_kernel(const float* __restrict__ projf,
                   const float* __restrict__ gamma, const float* __restrict__ beta,
                   __half* __restrict__ xs2) {
    __shared__ float xs[16][128];
    __shared__ float mu_s[16], rs_s[16];
    long tok0 = (long)blockIdx.x * 16;
    int j = threadIdx.x;
    #pragma unroll
    for (int t=0;t<16;t++) {
        float v = projf[(tok0+t)*128 + j];
        xs[t][j] = v / (1.0f + __expf(-v));
    }
    __syncthreads();
    int warp = j >> 5, lane = j & 31;
    for (int t = warp*4; t < warp*4+4; t++) {
        float a0 = xs[t][lane], a1 = xs[t][lane+32], a2 = xs[t][lane+64], a3 = xs[t][lane+96];
        float s = a0+a1+a2+a3;
        float q = a0*a0+a1*a1+a2*a2+a3*a3;
        #pragma unroll
        for (int off=16; off; off>>=1) {
            s += __shfl_xor_sync(0xffffffff, s, off);
            q += __shfl_xor_sync(0xffffffff, q, off);
        }
        if (lane==0) {
            float mu = s * (1.0f/128.0f);
            float var = q * (1.0f/128.0f) - mu*mu;
            mu_s[t] = mu;
            rs_s[t] = rsqrtf(var + 1e-5f);
        }
    }
    __syncthreads();
    float g = gamma[j], bt = beta[j];
    #pragma unroll
    for (int t=0;t<16;t++) {
        float v = (xs[t][j]-mu_s[t])*rs_s[t]*g + bt;
        __half hi, lo;
        split_h(v, hi, lo);
        xs2[(tok0+t)*256 + j]       = hi;
        xs2[(tok0+t)*256 + 128 + j] = lo;
    }
}

// -------------------- attention core --------------------
__global__ __launch_bounds__(128)
void attn_core(const float* __restrict__ qkv, __half* __restrict__ ao) {
    __shared__ float qs[16][384];
    int bid = blockIdx.x;
    int b = bid >> 10, hw = bid & 1023;
    int tid = threadIdx.x;
    for (int idx = tid; idx < 16*96; idx += 128) {
        int t = idx / 96, f = idx % 96;
        ((float4*)qs[t])[f] =
            ((const float4*)(qkv + ((long)(b*16+t)*1024 + hw)*384))[f];
    }
    __syncthreads();
    int i = tid >> 4, srow = tid & 15;
    float qd[16];
    #pragma unroll
    for (int d=0; d<16; d++) qd[d] = qs[srow][i*48+d];
    float sc[16];
    float mx = -1e30f;
    #pragma unroll
    for (int l=0;l<16;l++) {
        float sv = 0.f;
        #pragma unroll
        for (int d=0;d<16;d++) sv += qd[d]*qs[l][i*48+16+d];
        sv = sv*0.25f + (l<=srow ? 1.0f : -1000.0f);
        sc[l]=sv; mx = fmaxf(mx, sv);
    }
    float sum=0.f;
    #pragma unroll
    for (int l=0;l<16;l++){ sc[l]=__expf(sc[l]-mx); sum+=sc[l]; }
    float inv = 1.0f/sum;
    float o[16];
    #pragma unroll
    for (int d=0;d<16;d++) o[d]=0.f;
    #pragma unroll
    for (int l=0;l<16;l++) {
        float wl = sc[l]*inv;
        #pragma unroll
        for (int d=0;d<16;d++) o[d] += wl*qs[l][i*48+32+d];
    }
    long t = (long)(b*16+srow)*1024 + hw;
    #pragma unroll
    for (int d=0;d<16;d++) {
        __half hi, lo;
        split_h(o[d], hi, lo);
        ao[t*256 + i*16 + d]       = hi;
        ao[t*256 + 128 + i*16 + d] = lo;
    }
}

// -------------------- universal warp-MMA GEMM (parallel parts) --------------------
#define ROWB 144
#define STAGE_A (128*ROWB)
#define STAGE   (2*STAGE_A)
#define NSTAGE  4
#define GEMM_SMEM (NSTAGE*STAGE)  // 147456

template<int NTAP, int EPI>
__global__ __launch_bounds__(512, 1)
void gemm_mma(const __half* __restrict__ A, const __half* __restrict__ Bw,
              float* __restrict__ Out, int ldo,
              const float* __restrict__ aux, __half* __restrict__ outh,
              long a_bstride, long a_zstride, long o_zstride) {
    constexpr int ALEN   = (NTAP == 9) ? 128 : 256;
    constexpr int CPT    = ALEN / 64;
    constexpr int NCHUNK = NTAP * CPT;
    extern __shared__ char smem[];
    uint32_t sb = smem_u32(smem);

    int tid = threadIdx.x;
    int m0 = blockIdx.x * 128;
    int n0 = blockIdx.y * 128;
    int z  = blockIdx.z;

    int lrow = tid >> 2;
    int lseg = (tid & 3) * 2;
    int p = m0 + lrow;
    int bb = p >> 10, pix = p & 1023;
    int y = pix >> 5, x = pix & 31;
    long arow_base = (long)bb * a_bstride + (long)z * a_zstride;

    auto load_chunk = [&](int c, int st) {
        int koff = (c % CPT) * 64;
        bool v = true;
        long arow;
        if (NTAP == 9) {
            int tap = c / CPT;
            int ky = tap/3 - 1, kx = tap%3 - 1;
            int yy = y + ky, xx = x + kx;
            v = ((unsigned)yy < 32u) && ((unsigned)xx < 32u);
            arow = arow_base + ((yy<<5) + xx);
        } else {
            arow = arow_base + pix;
        }
        const __half* asrc = v ? (A + arow*ALEN + koff + lseg*8) : A;
        uint32_t ab = sb + st*STAGE + lrow*ROWB + lseg*16;
        cp16(ab,      asrc,     v);
        cp16(ab + 16, asrc + 8, v);
        const __half* bsrc = Bw + (long)(n0 + lrow)*(NTAP*ALEN) + c*64 + lseg*8;
        uint32_t bbs = sb + st*STAGE + STAGE_A + lrow*ROWB + lseg*16;
        cp16(bbs,      bsrc,     true);
        cp16(bbs + 16, bsrc + 8, true);
        CP_COMMIT();
    };

    int w = tid >> 5, l = tid & 31;
    int m_off = (w >> 2) * 32;
    int n_off = (w & 3) * 32;
    int lr = l & 15, lh = (l >> 4) << 4;

    float acc[2][4][4];
    #pragma unroll
    for (int i=0;i<2;i++)
        #pragma unroll
        for (int j=0;j<4;j++)
            #pragma unroll
            for (int q=0;q<4;q++) acc[i][j][q]=0.f;

    load_chunk(0, 0);
    if (NCHUNK > 1) load_chunk(1, 1); else CP_COMMIT();
    if (NCHUNK > 2) load_chunk(2, 2); else CP_COMMIT();

    for (int c = 0; c < NCHUNK; c++) {
        int st = c & (NSTAGE-1);
        if (c + 3 < NCHUNK) load_chunk(c + 3, (c + 3) & (NSTAGE-1));
        else CP_COMMIT();
        CP_WAIT3();
        __syncthreads();

        uint32_t a_st = sb + st*STAGE;
        uint32_t b_st = a_st + STAGE_A;
        #pragma unroll
        for (int ks = 0; ks < 4; ks++) {
            uint32_t af[2][4], bf[2][4];
            #pragma unroll
            for (int mt = 0; mt < 2; mt++)
                ldm_x4(af[mt], a_st + (m_off + mt*16 + lr)*ROWB + ks*32 + lh);
            #pragma unroll
            for (int nt = 0; nt < 2; nt++)
                ldm_x4(bf[nt], b_st + (n_off + nt*16 + lr)*ROWB + ks*32 + lh);
            #pragma unroll
            for (int mt = 0; mt < 2; mt++) {
                #pragma unroll
                for (int n8 = 0; n8 < 4; n8++) {
                    int nt = n8 >> 1, hi = n8 & 1;
                    mma16816(acc[mt][n8], af[mt], bf[nt][hi], bf[nt][2+hi]);
                }
            }
        }
        __syncthreads();
    }

    #pragma unroll
    for (int mt = 0; mt < 2; mt++) {
        int r0 = m0 + m_off + mt*16 + (l >> 2);
        #pragma unroll
        for (int n8 = 0; n8 < 4; n8++) {
            int cc = n0 + n_off + n8*8 + (l & 3)*2;
            float d0 = acc[mt][n8][0], d1 = acc[mt][n8][1];
            float d2 = acc[mt][n8][2], d3 = acc[mt][n8][3];
            if (EPI == 2) {
                float v0 = d0 + aux[(long)r0*128 + cc];
                float v1 = d1 + aux[(long)r0*128 + cc + 1];
                float v2 = d2 + aux[(long)(r0+8)*128 + cc];
                float v3 = d3 + aux[(long)(r0+8)*128 + cc + 1];
                outh[(long)r0*128 + cc]         = __float2half(v0);
                outh[(long)r0*128 + cc + 1]     = __float2half(v1);
                outh[(long)(r0+8)*128 + cc]     = __float2half(v2);
                outh[(long)(r0+8)*128 + cc + 1] = __float2half(v3);
            } else {
                float* p0 = Out + ((long)z*o_zstride + r0    )*ldo + cc;
                float* p1 = Out + ((long)z*o_zstride + r0 + 8)*ldo + cc;
                p0[0] = d0; p0[1] = d1;
                p1[0] = d2; p1[1] = d3;
            }
        }
    }
}

// -------------------- persistent ConvLSTM chain --------------------
// 128 CTAs (1/SM, all resident). CTA = (m = bid>>1, nh = bid&1), tile 128 x 256.
// Each step: conv_h tile accumulated into ccx[s]; rowblock counter; winner fuses gates.
#define CROWB 144
#define CSTAGE_A (128*CROWB)        // 18432
#define CSTAGE_B (256*CROWB)        // 36864
#define CSTAGE   (CSTAGE_A + CSTAGE_B)
#define CNSTAGE  3
#define CHAIN_SMEM (CNSTAGE*CSTAGE) // 165888

__device__ __forceinline__ void grid_barrier(int nct) {
    __syncthreads();
    if (threadIdx.x == 0) {
        __threadfence();
        int target = g_sense + 1;     // monotonically increasing epochs
        int arrived = atomicAdd(&g_barcnt, 1);
        if (arrived == nct - 1) {
            g_barcnt = 0;
            __threadfence();
            g_sense = target;
        } else {
            while (g_sense < target) { }
        }
        __threadfence();
    }
    __syncthreads();
}

__global__ __launch_bounds__(512, 1)
void chain_kernel(const __half* __restrict__ Bw,
                  float* __restrict__ ccx, float* __restrict__ cbuf,
                  __half* __restrict__ hp0, __half* __restrict__ hp1,
                  float* __restrict__ out) {
    extern __shared__ char smem[];
    uint32_t sb = smem_u32(smem);
    int tid = threadIdx.x;
    int m = blockIdx.x >> 1;
    int nh = blockIdx.x & 1;
    int n0 = nh * 256;
    __half* hps[2] = {hp0, hp1};

    // ---- gates helper (512 threads cover 128 rows x 128 e) ----
    auto do_gates = [&](int s) {
        __half* hw = hps[s & 1];
        int r = tid >> 2;
        int e0 = (tid & 3) * 32;
        int p = m*128 + r;
        const float* row = ccx + ((long)s*Pn + p)*OC;
        float* crow = cbuf + (long)p*128;
        __half* hrow = hw + (long)p*128;
        int b = p >> 10, pix = p & 1023;
        float* orow = out + ((long)(b*16+s)*1024 + pix)*128;
        #pragma unroll 8
        for (int j = 0; j < 32; j++) {
            int e = e0 + j;
            float ci = row[e], cf = row[128+e], co = row[256+e], cg = row[384+e];
            float si = 1.f/(1.f+__expf(-ci));
            float sf = 1.f/(1.f+__expf(-cf));
            float so = 1.f/(1.f+__expf(-co));
            float c_prev = cbuf == nullptr ? 0.f : crow[e];
            float c_next = sf*c_prev + si*tanhf(cg);
            float h_next = so*tanhf(c_next);
            crow[e] = c_next;
            hrow[e] = __float2half(h_next);
            orow[e] = h_next;
        }
    };

    // ---- step 0: gates only (c=0 state pre-zeroed by zero_kernel) ----
    if (nh == 0) do_gates(0);
    grid_barrier(128);

    // ---- MMA geometry: 16 warps, warp tile 32x64 ----
    int w = tid >> 5, l = tid & 31;
    int m_off = (w >> 2) * 32;
    int n_off = (w & 3) * 64;
    int lr = l & 15, lh = (l >> 4) << 4;

    for (int s = 1; s < Sn; s++) {
        const __half* A = hps[(s-1) & 1];
        float* Out_s = ccx + (long)s*Pn*OC;

        auto load_chunk = [&](int c, int st) {
            int tap = c >> 1;
            int koff = (c & 1) * 64;
            int ky = tap/3 - 1, kx = tap%3 - 1;
            uint32_t a_st = sb + st*CSTAGE;
            uint32_t b_st = a_st + CSTAGE_A;
            // A: 128 rows x 8 segs = 1024 units; 2 per thread
            #pragma unroll
            for (int i = 0; i < 2; i++) {
                int id = tid + i*512;
                int row = id >> 3, seg = id & 7;
                int p = m*128 + row;
                int y = (p >> 5) & 31, x = p & 31;
                int yy = y + ky, xx = x + kx;
                bool v = ((unsigned)yy < 32u) && ((unsigned)xx < 32u);
                const __half* asrc = v
                    ? (A + ((long)(p >> 10)*1024 + (yy<<5) + xx)*128 + koff + seg*8)
                    : (const __half*)A;
                cp16(a_st + row*CROWB + seg*16, asrc, v);
            }
            // B: 256 rows x 8 segs = 2048 units; 4 per thread
            #pragma unroll
            for (int i = 0; i < 4; i++) {
                int id = tid + i*512;
                int row = id >> 3, seg = id & 7;
                const __half* bsrc = Bw + (long)(n0 + row)*1152 + c*64 + seg*8;
                cp16(b_st + row*CROWB + seg*16, bsrc, true);
            }
            CP_COMMIT();
        };

        float acc[2][8][4];
        #pragma unroll
        for (int i=0;i<2;i++)
            #pragma unroll
            for (int j=0;j<8;j++)
                #pragma unroll
                for (int q=0;q<4;q++) acc[i][j][q]=0.f;

        load_chunk(0, 0);
        load_chunk(1, 1);

        for (int c = 0; c < 18; c++) {
            int st = c % CNSTAGE;
            if (c + 2 < 18) load_chunk(c + 2, (c + 2) % CNSTAGE);
            else CP_COMMIT();
            CP_WAIT2();
            __syncthreads();

            uint32_t a_st = sb + st*CSTAGE;
            uint32_t b_st = a_st + CSTAGE_A;
            #pragma unroll
            for (int ks = 0; ks < 4; ks++) {
                uint32_t af[2][4], bf[4][4];
                #pragma unroll
                for (int mt = 0; mt < 2; mt++)
                    ldm_x4(af[mt], a_st + (m_off + mt*16 + lr)*CROWB + ks*32 + lh);
                #pragma unroll
                for (int nt = 0; nt < 4; nt++)
                    ldm_x4(bf[nt], b_st + (n_off + nt*16 + lr)*CROWB + ks*32 + lh);
                #pragma unroll
                for (int mt = 0; mt < 2; mt++) {
                    #pragma unroll
                    for (int n8 = 0; n8 < 8; n8++) {
                        int nt = n8 >> 1, hi = n8 & 1;
                        mma16816(acc[mt][n8], af[mt], bf[nt][hi], bf[nt][2+hi]);
                    }
                }
            }
            __syncthreads();
        }

        // epilogue: accumulate into ccx[s]
        #pragma unroll
        for (int mt = 0; mt < 2; mt++) {
            int r0 = m*128 + m_off + mt*16 + (l >> 2);
            #pragma unroll
            for (int n8 = 0; n8 < 8; n8++) {
                int cc = n0 + n_off + n8*8 + (l & 3)*2;
                float* p0 = Out_s + (long)r0*OC + cc;
                float* p1 = Out_s + (long)(r0+8)*OC + cc;
                p0[0] += acc[mt][n8][0]; p0[1] += acc[mt][n8][1];
                p1[0] += acc[mt][n8][2]; p1[1] += acc[mt][n8][3];
            }
        }

        // rowblock arrival -> winner fuses gates
        __syncthreads();
        __shared__ int s_win;
        if (tid == 0) {
            __threadfence();
            int old = atomicAdd(&g_cnt[m], 1);
            s_win = (old == 1);
            if (old == 1) { g_cnt[m] = 0; __threadfence(); }
        }
        __syncthreads();
        if (s_win) do_gates(s);
        grid_barrier(128);
    }
}

// -------------------- launch --------------------
extern "C" void kernel_launch(void* const* d_in, const int* in_sizes, int n_in,
                              void* d_out, int out_size) {
    const float* inputs  = (const float*)d_in[0];
    const float* W_proj  = (const float*)d_in[1];
    const float* ln_g    = (const float*)d_in[2];
    const float* ln_b    = (const float*)d_in[3];
    const float* W_in    = (const float*)d_in[4];
    const float* W_out   = (const float*)d_in[5];
    const float* conv_k  = (const float*)d_in[6];
    float* out = (float*)d_out;

    float *projf, *qkv, *ccx, *cb;
    __half *xin2, *xs2, *ao, *xp, *hp0, *hp1, *bx, *bh, *bproj, *bqkv, *bout;
    cudaGetSymbolAddress((void**)&projf, g_projf);
    cudaGetSymbolAddress((void**)&qkv, g_qkv);
    cudaGetSymbolAddress((void**)&ccx, g_ccx);
    cudaGetSymbolAddress((void**)&cb,  g_c);
    cudaGetSymbolAddress((void**)&xin2, g_xin2);
    cudaGetSymbolAddress((void**)&xs2, g_xs2);
    cudaGetSymbolAddress((void**)&ao,  g_ao);
    cudaGetSymbolAddress((void**)&xp,  g_xp);
    cudaGetSymbolAddress((void**)&hp0, g_hpp);
    hp1 = hp0 + (long)Pn*128;
    cudaGetSymbolAddress((void**)&bx,  g_bx);
    cudaGetSymbolAddress((void**)&bh,  g_bh);
    cudaGetSymbolAddress((void**)&bproj, g_bproj);
    cudaGetSymbolAddress((void**)&bqkv, g_bqkv);
    cudaGetSymbolAddress((void**)&bout, g_bout);

    cudaFuncSetAttribute(gemm_mma<1,0>, cudaFuncAttributeMaxDynamicSharedMemorySize, GEMM_SMEM);
    cudaFuncSetAttribute(gemm_mma<1,2>, cudaFuncAttributeMaxDynamicSharedMemorySize, GEMM_SMEM);
    cudaFuncSetAttribute(gemm_mma<9,0>, cudaFuncAttributeMaxDynamicSharedMemorySize, GEMM_SMEM);
    cudaFuncSetAttribute(chain_kernel,  cudaFuncAttributeMaxDynamicSharedMemorySize, CHAIN_SMEM);

    zero_kernel<<<(Pn*En+255)/256, 256>>>(cb, Pn*En);
    reorder_conv<<<(int)(((long)OC*1152 + 255)/256), 256>>>(conv_k, bx, bh);
    reorder_w2<128><<<(128*128+255)/256, 256>>>(W_proj, bproj);
    reorder_w2<384><<<(384*128+255)/256, 256>>>(W_in, bqkv);
    reorder_w2<128><<<(128*128+255)/256, 256>>>(W_out, bout);
    split_in<<<(int)(((long)TOK*128+255)/256), 256>>>(inputs, xin2);

    // proj = inputs @ W_proj (2-term)
    gemm_mma<1,0><<<dim3(TOK/128, 1, 1), 512, GEMM_SMEM>>>(
        xin2, bproj, projf, 128, nullptr, nullptr, 1024L, 0L, 0L);

    siluln_kernel<<<TOK/16, 128>>>(projf, ln_g, ln_b, xs2);

    // qkv = xln @ W_in (2-term)
    gemm_mma<1,0><<<dim3(TOK/128, 3, 1), 512, GEMM_SMEM>>>(
        xs2, bqkv, qkv, 384, nullptr, nullptr, 1024L, 0L, 0L);

    attn_core<<<Pn, 128>>>(qkv, ao);

    // xres = ao @ W_out + inputs -> 1-term fp16 xp
    gemm_mma<1,2><<<dim3(TOK/128, 1, 1), 512, GEMM_SMEM>>>(
        ao, bout, nullptr, 0, inputs, xp, 1024L, 0L, 0L);

    // batch-parallel conv_x over all 16 steps (1-term)
    gemm_mma<9,0><<<dim3(Pn/128, 4, Sn), 512, GEMM_SMEM>>>(
        xp, bx, ccx, OC, nullptr, nullptr, 16384L, 1024L, 8192L);

    // persistent ConvLSTM chain: conv_h + fused gates, grid-sync between steps
    chain_kernel<<<128, 512, CHAIN_SMEM>>>(bh, ccx, cb, hp0, hp1, out);
}

// round 7
// speedup vs baseline: 1.0096x; 1.0096x over previous
#include <cuda_runtime.h>
#include <cuda_fp16.h>
#include <cstdint>

// Problem constants
#define Bn 8
#define Sn 16
#define En 128
#define TOK (Bn*Sn*32*32)      // 131072
#define Pn (Bn*32*32)          // 8192
#define OC 512

// -------- scratch (device globals) --------
__device__ float g_projf[(long)TOK*128];
__device__ float g_qkv[(long)TOK*384];
__device__ float g_ccx[(long)TOK*OC];
__device__ float g_c[Pn*En];
__device__ __half g_xin2[(long)TOK*256];
__device__ __half g_xs2[(long)TOK*256];
__device__ __half g_ao[(long)TOK*256];
__device__ __half g_xp[(long)TOK*128];
__device__ __half g_hpp[2][Pn*128];           // ping-pong h
__device__ __half g_bx[(long)OC*1152];
__device__ __half g_bh[(long)OC*1152];
__device__ __half g_bproj[128*256];
__device__ __half g_bqkv[384*256];
__device__ __half g_bout[128*256];
__device__ int g_cnt[64];     // conv_h arrival counters
__device__ int g_cnt0[64];    // conv_x (z==0) arrival counters

// ==================== helpers ====================
__device__ __forceinline__ uint32_t smem_u32(const void* p) {
    uint32_t a;
    asm("{ .reg .u64 t; cvta.to.shared.u64 t, %1; cvt.u32.u64 %0, t; }" : "=r"(a) : "l"(p));
    return a;
}
__device__ __forceinline__ void cp16(uint32_t dst, const void* src, bool pred) {
    asm volatile("cp.async.cg.shared.global [%0], [%1], 16, %2;"
        :: "r"(dst), "l"(src), "r"(pred ? 16u : 0u));
}
#define CP_COMMIT() asm volatile("cp.async.commit_group;" ::: "memory")
#define CP_WAIT3()  asm volatile("cp.async.wait_group 3;" ::: "memory")

__device__ __forceinline__ void ldm_x4(uint32_t* r, uint32_t addr) {
    asm volatile("ldmatrix.sync.aligned.m8n8.x4.shared.b16 {%0,%1,%2,%3}, [%4];"
        : "=r"(r[0]), "=r"(r[1]), "=r"(r[2]), "=r"(r[3]) : "r"(addr));
}
__device__ __forceinline__ void mma16816(float* d, const uint32_t* a, uint32_t b0, uint32_t b1) {
    asm volatile("mma.sync.aligned.m16n8k16.row.col.f32.f16.f16.f32 "
        "{%0,%1,%2,%3}, {%4,%5,%6,%7}, {%8,%9}, {%0,%1,%2,%3};"
        : "+f"(d[0]), "+f"(d[1]), "+f"(d[2]), "+f"(d[3])
        : "r"(a[0]), "r"(a[1]), "r"(a[2]), "r"(a[3]), "r"(b0), "r"(b1));
}
__device__ __forceinline__ void split_h(float x, __half& hi, __half& lo) {
    hi = __float2half(x);
    lo = __float2half(x - __half2float(hi));
}

// fused LSTM gates for rows m*128..m*128+127 (512 threads)
__device__ __forceinline__ void gates_block(const float* __restrict__ ccs,
                                            float* __restrict__ cbuf, bool czero,
                                            __half* __restrict__ hp,
                                            float* __restrict__ out,
                                            int s, int m, int tid) {
    int r = tid >> 2;
    int e0 = (tid & 3) * 32;
    int p = m*128 + r;
    const float* row = ccs + (long)p*OC;
    float* crow = cbuf + (long)p*128;
    __half* hrow = hp + (long)p*128;
    int b = p >> 10, pix = p & 1023;
    float* orow = out + ((long)(b*16+s)*1024 + pix)*128;
    #pragma unroll 8
    for (int j = 0; j < 32; j++) {
        int e = e0 + j;
        float ci = row[e], cf = row[128+e], co = row[256+e], cg = row[384+e];
        float si = 1.f/(1.f+__expf(-ci));
        float sf = 1.f/(1.f+__expf(-cf));
        float so = 1.f/(1.f+__expf(-co));
        float c_prev = czero ? 0.f : crow[e];
        float c_next = sf*c_prev + si*tanhf(cg);
        float h_next = so*tanhf(c_next);
        crow[e] = c_next;
        hrow[e] = __float2half(h_next);
        orow[e] = h_next;
    }
}

// -------------------- small kernels --------------------
__global__ void init_kernel() {
    if (threadIdx.x < 64) { g_cnt[threadIdx.x] = 0; g_cnt0[threadIdx.x] = 0; }
}
__global__ void split_in(const float* __restrict__ inp, __half* __restrict__ x2) {
    long idx = (long)blockIdx.x*blockDim.x + threadIdx.x;
    if (idx >= (long)TOK*128) return;
    long row = idx >> 7; int e = idx & 127;
    __half hi, lo;
    split_h(inp[idx], hi, lo);
    x2[row*256 + e]       = hi;
    x2[row*256 + 128 + e] = lo;
}
__global__ void reorder_conv(const float* __restrict__ ck,
                             __half* __restrict__ bx, __half* __restrict__ bh) {
    long idx = (long)blockIdx.x*blockDim.x + threadIdx.x;
    if (idx >= (long)OC*1152) return;
    int oc = idx / 1152, k = idx % 1152;
    int tap = k >> 7, ic = k & 127;
    int ky = tap / 3, kx = tap % 3;
    bx[idx] = __float2half(ck[(((long)oc*256 + ic      )*3 + ky)*3 + kx]);
    bh[idx] = __float2half(ck[(((long)oc*256 + 128 + ic)*3 + ky)*3 + kx]);
}
// merged dense-weight reorder: proj(128) | qkv(384) | out(128), 2-term [w|w]
__global__ void reorder_dense(const float* __restrict__ wp, const float* __restrict__ wi,
                              const float* __restrict__ wo,
                              __half* __restrict__ bp, __half* __restrict__ bi,
                              __half* __restrict__ bo) {
    int idx = blockIdx.x*blockDim.x + threadIdx.x;
    if (idx >= 640*128) return;
    int n = idx >> 7, k = idx & 127;
    const float* w; __half* b; int nn, N;
    if (n < 128)      { w = wp; b = bp; nn = n;       N = 128; }
    else if (n < 512) { w = wi; b = bi; nn = n - 128; N = 384; }
    else              { w = wo; b = bo; nn = n - 512; N = 128; }
    __half v = __float2half(w[k*N + nn]);
    b[nn*256 + k]       = v;
    b[nn*256 + 128 + k] = v;
}

// -------------------- silu + LN --------------------
__global__ __launch_bounds__(128)
void siluln_kernel(const float* __restrict__ projf,
                   const float* __restrict__ gamma, const float* __restrict__ beta,
                   __half* __restrict__ xs2) {
    __shared__ float xs[16][128];
    __shared__ float mu_s[16], rs_s[16];
    long tok0 = (long)blockIdx.x * 16;
    int j = threadIdx.x;
    #pragma unroll
    for (int t=0;t<16;t++) {
        float v = projf[(tok0+t)*128 + j];
        xs[t][j] = v / (1.0f + __expf(-v));
    }
    __syncthreads();
    int warp = j >> 5, lane = j & 31;
    for (int t = warp*4; t < warp*4+4; t++) {
        float a0 = xs[t][lane], a1 = xs[t][lane+32], a2 = xs[t][lane+64], a3 = xs[t][lane+96];
        float s = a0+a1+a2+a3;
        float q = a0*a0+a1*a1+a2*a2+a3*a3;
        #pragma unroll
        for (int off=16; off; off>>=1) {
            s += __shfl_xor_sync(0xffffffff, s, off);
            q += __shfl_xor_sync(0xffffffff, q, off);
        }
        if (lane==0) {
            float mu = s * (1.0f/128.0f);
            float var = q * (1.0f/128.0f) - mu*mu;
            mu_s[t] = mu;
            rs_s[t] = rsqrtf(var + 1e-5f);
        }
    }
    __syncthreads();
    float g = gamma[j], bt = beta[j];
    #pragma unroll
    for (int t=0;t<16;t++) {
        float v = (xs[t][j]-mu_s[t])*rs_s[t]*g + bt;
        __half hi, lo;
        split_h(v, hi, lo);
        xs2[(tok0+t)*256 + j]       = hi;
        xs2[(tok0+t)*256 + 128 + j] = lo;
    }
}

// -------------------- attention core --------------------
__global__ __launch_bounds__(128)
void attn_core(const float* __restrict__ qkv, __half* __restrict__ ao) {
    __shared__ float qs[16][384];
    int bid = blockIdx.x;
    int b = bid >> 10, hw = bid & 1023;
    int tid = threadIdx.x;
    for (int idx = tid; idx < 16*96; idx += 128) {
        int t = idx / 96, f = idx % 96;
        ((float4*)qs[t])[f] =
            ((const float4*)(qkv + ((long)(b*16+t)*1024 + hw)*384))[f];
    }
    __syncthreads();
    int i = tid >> 4, srow = tid & 15;
    float qd[16];
    #pragma unroll
    for (int d=0; d<16; d++) qd[d] = qs[srow][i*48+d];
    float sc[16];
    float mx = -1e30f;
    #pragma unroll
    for (int l=0;l<16;l++) {
        float sv = 0.f;
        #pragma unroll
        for (int d=0;d<16;d++) sv += qd[d]*qs[l][i*48+16+d];
        sv = sv*0.25f + (l<=srow ? 1.0f : -1000.0f);
        sc[l]=sv; mx = fmaxf(mx, sv);
    }
    float sum=0.f;
    #pragma unroll
    for (int l=0;l<16;l++){ sc[l]=__expf(sc[l]-mx); sum+=sc[l]; }
    float inv = 1.0f/sum;
    float o[16];
    #pragma unroll
    for (int d=0;d<16;d++) o[d]=0.f;
    #pragma unroll
    for (int l=0;l<16;l++) {
        float wl = sc[l]*inv;
        #pragma unroll
        for (int d=0;d<16;d++) o[d] += wl*qs[l][i*48+32+d];
    }
    long t = (long)(b*16+srow)*1024 + hw;
    #pragma unroll
    for (int d=0;d<16;d++) {
        __half hi, lo;
        split_h(o[d], hi, lo);
        ao[t*256 + i*16 + d]       = hi;
        ao[t*256 + 128 + i*16 + d] = lo;
    }
}

// -------------------- universal warp-MMA fp16 GEMM / implicit conv --------------------
// CTA 128x128, 16 warps 32x32, chunks of 64, 4-stage cp.async.
// NTAP=1 dense (A rows 256, 2-term). NTAP=9 conv gather (A rows 128, 1-term).
// EPI: 0 store f32 | 1 accumulate f32 | 2 +residual -> fp16 (xp)
//      3 accumulate + fused gates (conv_h) | 4 store + fused gates at z==0 (conv_x)
#define ROWB 144
#define STAGE_A (128*ROWB)
#define STAGE   (2*STAGE_A)
#define NSTAGE  4
#define GEMM_SMEM (NSTAGE*STAGE)  // 147456

template<int NTAP, int EPI>
__global__ __launch_bounds__(512, 1)
void gemm_mma(const __half* __restrict__ A, const __half* __restrict__ Bw,
              float* __restrict__ Out, int ldo,
              const float* __restrict__ aux, __half* __restrict__ outh,
              long a_bstride, long a_zstride, long o_zstride,
              float* cbuf, __half* hpo, float* outp, int* cnt, int sgate) {
    constexpr int ALEN   = (NTAP == 9) ? 128 : 256;
    constexpr int CPT    = ALEN / 64;
    constexpr int NCHUNK = NTAP * CPT;
    extern __shared__ char smem[];
    uint32_t sb = smem_u32(smem);

    int tid = threadIdx.x;
    int m0 = blockIdx.x * 128;
    int n0 = blockIdx.y * 128;
    int z  = blockIdx.z;

    int lrow = tid >> 2;
    int lseg = (tid & 3) * 2;
    int p = m0 + lrow;
    int bb = p >> 10, pix = p & 1023;
    int y = pix >> 5, x = pix & 31;
    long arow_base = (long)bb * a_bstride + (long)z * a_zstride;

    auto load_chunk = [&](int c, int st) {
        int koff = (c % CPT) * 64;
        bool v = true;
        long arow;
        if (NTAP == 9) {
            int tap = c / CPT;
            int ky = tap/3 - 1, kx = tap%3 - 1;
            int yy = y + ky, xx = x + kx;
            v = ((unsigned)yy < 32u) && ((unsigned)xx < 32u);
            arow = arow_base + ((yy<<5) + xx);
        } else {
            arow = arow_base + pix;
        }
        const __half* asrc = v ? (A + arow*ALEN + koff + lseg*8) : A;
        uint32_t ab = sb + st*STAGE + lrow*ROWB + lseg*16;
        cp16(ab,      asrc,     v);
        cp16(ab + 16, asrc + 8, v);
        const __half* bsrc = Bw + (long)(n0 + lrow)*(NTAP*ALEN) + c*64 + lseg*8;
        uint32_t bbs = sb + st*STAGE + STAGE_A + lrow*ROWB + lseg*16;
        cp16(bbs,      bsrc,     true);
        cp16(bbs + 16, bsrc + 8, true);
        CP_COMMIT();
    };

    int w = tid >> 5, l = tid & 31;
    int m_off = (w >> 2) * 32;
    int n_off = (w & 3) * 32;
    int lr = l & 15, lh = (l >> 4) << 4;

    float acc[2][4][4];
    #pragma unroll
    for (int i=0;i<2;i++)
        #pragma unroll
        for (int j=0;j<4;j++)
            #pragma unroll
            for (int q=0;q<4;q++) acc[i][j][q]=0.f;

    load_chunk(0, 0);
    if (NCHUNK > 1) load_chunk(1, 1); else CP_COMMIT();
    if (NCHUNK > 2) load_chunk(2, 2); else CP_COMMIT();

    for (int c = 0; c < NCHUNK; c++) {
        int st = c & (NSTAGE-1);
        if (c + 3 < NCHUNK) load_chunk(c + 3, (c + 3) & (NSTAGE-1));
        else CP_COMMIT();
        CP_WAIT3();
        __syncthreads();

        uint32_t a_st = sb + st*STAGE;
        uint32_t b_st = a_st + STAGE_A;
        #pragma unroll
        for (int ks = 0; ks < 4; ks++) {
            uint32_t af[2][4], bf[2][4];
            #pragma unroll
            for (int mt = 0; mt < 2; mt++)
                ldm_x4(af[mt], a_st + (m_off + mt*16 + lr)*ROWB + ks*32 + lh);
            #pragma unroll
            for (int nt = 0; nt < 2; nt++)
                ldm_x4(bf[nt], b_st + (n_off + nt*16 + lr)*ROWB + ks*32 + lh);
            #pragma unroll
            for (int mt = 0; mt < 2; mt++) {
                #pragma unroll
                for (int n8 = 0; n8 < 4; n8++) {
                    int nt = n8 >> 1, hi = n8 & 1;
                    mma16816(acc[mt][n8], af[mt], bf[nt][hi], bf[nt][2+hi]);
                }
            }
        }
        __syncthreads();
    }

    #pragma unroll
    for (int mt = 0; mt < 2; mt++) {
        int r0 = m0 + m_off + mt*16 + (l >> 2);
        #pragma unroll
        for (int n8 = 0; n8 < 4; n8++) {
            int cc = n0 + n_off + n8*8 + (l & 3)*2;
            float d0 = acc[mt][n8][0], d1 = acc[mt][n8][1];
            float d2 = acc[mt][n8][2], d3 = acc[mt][n8][3];
            if (EPI == 2) {
                float v0 = d0 + aux[(long)r0*128 + cc];
                float v1 = d1 + aux[(long)r0*128 + cc + 1];
                float v2 = d2 + aux[(long)(r0+8)*128 + cc];
                float v3 = d3 + aux[(long)(r0+8)*128 + cc + 1];
                outh[(long)r0*128 + cc]         = __float2half(v0);
                outh[(long)r0*128 + cc + 1]     = __float2half(v1);
                outh[(long)(r0+8)*128 + cc]     = __float2half(v2);
                outh[(long)(r0+8)*128 + cc + 1] = __float2half(v3);
            } else {
                float* p0 = Out + ((long)z*o_zstride + r0    )*ldo + cc;
                float* p1 = Out + ((long)z*o_zstride + r0 + 8)*ldo + cc;
                if (EPI == 1 || EPI == 3) { d0 += p0[0]; d1 += p0[1]; d2 += p1[0]; d3 += p1[1]; }
                p0[0] = d0; p0[1] = d1;
                p1[0] = d2; p1[1] = d3;
            }
        }
    }

    // fused gates: last CTA of this row block runs the LSTM pointwise update
    if (EPI == 3 || EPI == 4) {
        if (EPI == 3 || z == 0) {
            __syncthreads();
            __shared__ int swin;
            if (tid == 0) {
                __threadfence();
                int old = atomicAdd(&cnt[blockIdx.x], 1);
                if (old == 3) { cnt[blockIdx.x] = 0; swin = 1; } else swin = 0;
            }
            __syncthreads();
            if (swin) {
                __threadfence();
                gates_block(Out, cbuf, sgate == 0, hpo, outp, sgate, blockIdx.x, tid);
            }
        }
    }
}

// -------------------- launch --------------------
extern "C" void kernel_launch(void* const* d_in, const int* in_sizes, int n_in,
                              void* d_out, int out_size) {
    const float* inputs  = (const float*)d_in[0];
    const float* W_proj  = (const float*)d_in[1];
    const float* ln_g    = (const float*)d_in[2];
    const float* ln_b    = (const float*)d_in[3];
    const float* W_in    = (const float*)d_in[4];
    const float* W_out   = (const float*)d_in[5];
    const float* conv_k  = (const float*)d_in[6];
    float* out = (float*)d_out;

    float *projf, *qkv, *ccx, *cb;
    __half *xin2, *xs2, *ao, *xp, *hp0, *hp1, *bx, *bh, *bproj, *bqkv, *bout;
    int *cnt, *cnt0;
    cudaGetSymbolAddress((void**)&projf, g_projf);
    cudaGetSymbolAddress((void**)&qkv, g_qkv);
    cudaGetSymbolAddress((void**)&ccx, g_ccx);
    cudaGetSymbolAddress((void**)&cb,  g_c);
    cudaGetSymbolAddress((void**)&xin2, g_xin2);
    cudaGetSymbolAddress((void**)&xs2, g_xs2);
    cudaGetSymbolAddress((void**)&ao,  g_ao);
    cudaGetSymbolAddress((void**)&xp,  g_xp);
    cudaGetSymbolAddress((void**)&hp0, g_hpp);
    hp1 = hp0 + (long)Pn*128;
    cudaGetSymbolAddress((void**)&bx,  g_bx);
    cudaGetSymbolAddress((void**)&bh,  g_bh);
    cudaGetSymbolAddress((void**)&bproj, g_bproj);
    cudaGetSymbolAddress((void**)&bqkv, g_bqkv);
    cudaGetSymbolAddress((void**)&bout, g_bout);
    cudaGetSymbolAddress((void**)&cnt,  g_cnt);
    cudaGetSymbolAddress((void**)&cnt0, g_cnt0);
    __half* hps[2] = {hp0, hp1};

    cudaFuncSetAttribute(gemm_mma<1,0>, cudaFuncAttributeMaxDynamicSharedMemorySize, GEMM_SMEM);
    cudaFuncSetAttribute(gemm_mma<1,2>, cudaFuncAttributeMaxDynamicSharedMemorySize, GEMM_SMEM);
    cudaFuncSetAttribute(gemm_mma<9,4>, cudaFuncAttributeMaxDynamicSharedMemorySize, GEMM_SMEM);
    cudaFuncSetAttribute(gemm_mma<9,3>, cudaFuncAttributeMaxDynamicSharedMemorySize, GEMM_SMEM);

    init_kernel<<<1, 64>>>();
    reorder_conv<<<(int)(((long)OC*1152 + 255)/256), 256>>>(conv_k, bx, bh);
    reorder_dense<<<(640*128+255)/256, 256>>>(W_proj, W_in, W_out, bproj, bqkv, bout);
    split_in<<<(int)(((long)TOK*128+255)/256), 256>>>(inputs, xin2);

    // proj = inputs @ W_proj (2-term)
    gemm_mma<1,0><<<dim3(TOK/128, 1, 1), 512, GEMM_SMEM>>>(
        xin2, bproj, projf, 128, nullptr, nullptr, 1024L, 0L, 0L,
        nullptr, nullptr, nullptr, nullptr, 0);

    siluln_kernel<<<TOK/16, 128>>>(projf, ln_g, ln_b, xs2);

    // qkv = xln @ W_in (2-term)
    gemm_mma<1,0><<<dim3(TOK/128, 3, 1), 512, GEMM_SMEM>>>(
        xs2, bqkv, qkv, 384, nullptr, nullptr, 1024L, 0L, 0L,
        nullptr, nullptr, nullptr, nullptr, 0);

    attn_core<<<Pn, 128>>>(qkv, ao);

    // xres = ao @ W_out + inputs -> 1-term fp16 xp
    gemm_mma<1,2><<<dim3(TOK/128, 1, 1), 512, GEMM_SMEM>>>(
        ao, bout, nullptr, 0, inputs, xp, 1024L, 0L, 0L,
        nullptr, nullptr, nullptr, nullptr, 0);

    // conv_x over all 16 steps; z==0 row-blocks fuse gates(s=0) when complete
    gemm_mma<9,4><<<dim3(Pn/128, 4, Sn), 512, GEMM_SMEM>>>(
        xp, bx, ccx, OC, nullptr, nullptr, 16384L, 1024L, 8192L,
        cb, hps[0], out, cnt0, 0);

    // sequential ConvLSTM: conv_h accumulates into ccx[s], last CTA per row block fuses gates(s)
    for (int s = 1; s < Sn; s++) {
        gemm_mma<9,3><<<dim3(Pn/128, 4, 1), 512, GEMM_SMEM>>>(
            hps[(s-1) & 1], bh, ccx + (long)s*Pn*OC, OC, nullptr, nullptr, 1024L, 0L, 0L,
            cb, hps[s & 1], out, cnt, s);
    }
}

// round 8
// speedup vs baseline: 1.5848x; 1.5697x over previous
#include <cuda_runtime.h>
#include <cuda_fp16.h>
#include <cstdint>

// Problem constants
#define Bn 8
#define Sn 16
#define En 128
#define TOK (Bn*Sn*32*32)      // 131072
#define Pn (Bn*32*32)          // 8192
#define OC 512

// -------- scratch (device globals) --------
__device__ float g_qkv[(long)TOK*384];
__device__ float g_ccx[(long)TOK*OC];
__device__ float g_c[Pn*En];
__device__ __half g_xin2[(long)TOK*256];
__device__ __half g_xs2[(long)TOK*256];
__device__ __half g_ao[(long)TOK*256];
__device__ __half g_xp[(long)TOK*128];
__device__ __half g_hp[Pn*128];
__device__ __half g_bx[(long)OC*1152];
__device__ __half g_bh[(long)OC*1152];
__device__ __half g_bproj[128*256];
__device__ __half g_bqkv[384*256];
__device__ __half g_bout[128*256];

// ==================== helpers ====================
__device__ __forceinline__ uint32_t smem_u32(const void* p) {
    uint32_t a;
    asm("{ .reg .u64 t; cvta.to.shared.u64 t, %1; cvt.u32.u64 %0, t; }" : "=r"(a) : "l"(p));
    return a;
}
__device__ __forceinline__ void cp16(uint32_t dst, const void* src, bool pred) {
    asm volatile("cp.async.cg.shared.global [%0], [%1], 16, %2;"
        :: "r"(dst), "l"(src), "r"(pred ? 16u : 0u));
}
#define CP_COMMIT() asm volatile("cp.async.commit_group;" ::: "memory")
#define CP_WAIT3()  asm volatile("cp.async.wait_group 3;" ::: "memory")
#define CP_WAIT2()  asm volatile("cp.async.wait_group 2;" ::: "memory")

__device__ __forceinline__ void ldm_x4(uint32_t* r, uint32_t addr) {
    asm volatile("ldmatrix.sync.aligned.m8n8.x4.shared.b16 {%0,%1,%2,%3}, [%4];"
        : "=r"(r[0]), "=r"(r[1]), "=r"(r[2]), "=r"(r[3]) : "r"(addr));
}
__device__ __forceinline__ void mma16816(float* d, const uint32_t* a, uint32_t b0, uint32_t b1) {
    asm volatile("mma.sync.aligned.m16n8k16.row.col.f32.f16.f16.f32 "
        "{%0,%1,%2,%3}, {%4,%5,%6,%7}, {%8,%9}, {%0,%1,%2,%3};"
        : "+f"(d[0]), "+f"(d[1]), "+f"(d[2]), "+f"(d[3])
        : "r"(a[0]), "r"(a[1]), "r"(a[2]), "r"(a[3]), "r"(b0), "r"(b1));
}
__device__ __forceinline__ void split_h(float x, __half& hi, __half& lo) {
    hi = __float2half(x);
    lo = __float2half(x - __half2float(hi));
}

// -------------------- small kernels --------------------
__global__ void split_in(const float* __restrict__ inp, __half* __restrict__ x2) {
    long idx = (long)blockIdx.x*blockDim.x + threadIdx.x;
    if (idx >= (long)TOK*128) return;
    long row = idx >> 7; int e = idx & 127;
    __half hi, lo;
    split_h(inp[idx], hi, lo);
    x2[row*256 + e]       = hi;
    x2[row*256 + 128 + e] = lo;
}
__global__ void reorder_conv(const float* __restrict__ ck,
                             __half* __restrict__ bx, __half* __restrict__ bh) {
    long idx = (long)blockIdx.x*blockDim.x + threadIdx.x;
    if (idx >= (long)OC*1152) return;
    int oc = idx / 1152, k = idx % 1152;
    int tap = k >> 7, ic = k & 127;
    int ky = tap / 3, kx = tap % 3;
    bx[idx] = __float2half(ck[(((long)oc*256 + ic      )*3 + ky)*3 + kx]);
    bh[idx] = __float2half(ck[(((long)oc*256 + 128 + ic)*3 + ky)*3 + kx]);
}
__global__ void reorder_dense(const float* __restrict__ wp, const float* __restrict__ wi,
                              const float* __restrict__ wo,
                              __half* __restrict__ bp, __half* __restrict__ bi,
                              __half* __restrict__ bo) {
    int idx = blockIdx.x*blockDim.x + threadIdx.x;
    if (idx >= 640*128) return;
    int n = idx >> 7, k = idx & 127;
    const float* w; __half* b; int nn, N;
    if (n < 128)      { w = wp; b = bp; nn = n;       N = 128; }
    else if (n < 512) { w = wi; b = bi; nn = n - 128; N = 384; }
    else              { w = wo; b = bo; nn = n - 512; N = 128; }
    __half v = __float2half(w[k*N + nn]);
    b[nn*256 + k]       = v;
    b[nn*256 + 128 + k] = v;
}

// -------------------- attention core --------------------
__global__ __launch_bounds__(128)
void attn_core(const float* __restrict__ qkv, __half* __restrict__ ao) {
    __shared__ float qs[16][384];
    int bid = blockIdx.x;
    int b = bid >> 10, hw = bid & 1023;
    int tid = threadIdx.x;
    for (int idx = tid; idx < 16*96; idx += 128) {
        int t = idx / 96, f = idx % 96;
        ((float4*)qs[t])[f] =
            ((const float4*)(qkv + ((long)(b*16+t)*1024 + hw)*384))[f];
    }
    __syncthreads();
    int i = tid >> 4, srow = tid & 15;
    float qd[16];
    #pragma unroll
    for (int d=0; d<16; d++) qd[d] = qs[srow][i*48+d];
    float sc[16];
    float mx = -1e30f;
    #pragma unroll
    for (int l=0;l<16;l++) {
        float sv = 0.f;
        #pragma unroll
        for (int d=0;d<16;d++) sv += qd[d]*qs[l][i*48+16+d];
        sv = sv*0.25f + (l<=srow ? 1.0f : -1000.0f);
        sc[l]=sv; mx = fmaxf(mx, sv);
    }
    float sum=0.f;
    #pragma unroll
    for (int l=0;l<16;l++){ sc[l]=__expf(sc[l]-mx); sum+=sc[l]; }
    float inv = 1.0f/sum;
    float o[16];
    #pragma unroll
    for (int d=0;d<16;d++) o[d]=0.f;
    #pragma unroll
    for (int l=0;l<16;l++) {
        float wl = sc[l]*inv;
        #pragma unroll
        for (int d=0;d<16;d++) o[d] += wl*qs[l][i*48+32+d];
    }
    long t = (long)(b*16+srow)*1024 + hw;
    #pragma unroll
    for (int d=0;d<16;d++) {
        __half hi, lo;
        split_h(o[d], hi, lo);
        ao[t*256 + i*16 + d]       = hi;
        ao[t*256 + 128 + i*16 + d] = lo;
    }
}

// -------------------- universal warp-MMA fp16 GEMM / implicit conv --------------------
// CTA 128x128, 16 warps 32x32, chunks of 64, 4-stage cp.async.
// NTAP=1 dense (A rows 256, 2-term). NTAP=9 conv gather (A rows 128, 1-term).
// EPI: 0 store f32 | 2 +residual -> fp16 | 5 silu+LN+split -> fp16 [hi|lo] (proj)
#define ROWB 144
#define STAGE_A (128*ROWB)
#define STAGE   (2*STAGE_A)
#define NSTAGE  4
#define GEMM_SMEM (NSTAGE*STAGE)  // 147456

template<int NTAP, int EPI>
__global__ __launch_bounds__(512, 1)
void gemm_mma(const __half* __restrict__ A, const __half* __restrict__ Bw,
              float* __restrict__ Out, int ldo,
              const float* __restrict__ aux, const float* __restrict__ aux2,
              __half* __restrict__ outh,
              long a_bstride, long a_zstride, long o_zstride) {
    constexpr int ALEN   = (NTAP == 9) ? 128 : 256;
    constexpr int CPT    = ALEN / 64;
    constexpr int NCHUNK = NTAP * CPT;
    extern __shared__ char smem[];
    uint32_t sb = smem_u32(smem);

    int tid = threadIdx.x;
    int m0 = blockIdx.x * 128;
    int n0 = blockIdx.y * 128;
    int z  = blockIdx.z;

    int lrow = tid >> 2;
    int lseg = (tid & 3) * 2;
    int p = m0 + lrow;
    int bb = p >> 10, pix = p & 1023;
    int y = pix >> 5, x = pix & 31;
    long arow_base = (long)bb * a_bstride + (long)z * a_zstride;

    auto load_chunk = [&](int c, int st) {
        int koff = (c % CPT) * 64;
        bool v = true;
        long arow;
        if (NTAP == 9) {
            int tap = c / CPT;
            int ky = tap/3 - 1, kx = tap%3 - 1;
            int yy = y + ky, xx = x + kx;
            v = ((unsigned)yy < 32u) && ((unsigned)xx < 32u);
            arow = arow_base + ((yy<<5) + xx);
        } else {
            arow = arow_base + pix;
        }
        const __half* asrc = v ? (A + arow*ALEN + koff + lseg*8) : A;
        uint32_t ab = sb + st*STAGE + lrow*ROWB + lseg*16;
        cp16(ab,      asrc,     v);
        cp16(ab + 16, asrc + 8, v);
        const __half* bsrc = Bw + (long)(n0 + lrow)*(NTAP*ALEN) + c*64 + lseg*8;
        uint32_t bbs = sb + st*STAGE + STAGE_A + lrow*ROWB + lseg*16;
        cp16(bbs,      bsrc,     true);
        cp16(bbs + 16, bsrc + 8, true);
        CP_COMMIT();
    };

    int w = tid >> 5, l = tid & 31;
    int m_off = (w >> 2) * 32;
    int n_off = (w & 3) * 32;
    int lr = l & 15, lh = (l >> 4) << 4;

    float acc[2][4][4];
    #pragma unroll
    for (int i=0;i<2;i++)
        #pragma unroll
        for (int j=0;j<4;j++)
            #pragma unroll
            for (int q=0;q<4;q++) acc[i][j][q]=0.f;

    load_chunk(0, 0);
    if (NCHUNK > 1) load_chunk(1, 1); else CP_COMMIT();
    if (NCHUNK > 2) load_chunk(2, 2); else CP_COMMIT();

    for (int c = 0; c < NCHUNK; c++) {
        int st = c & (NSTAGE-1);
        if (c + 3 < NCHUNK) load_chunk(c + 3, (c + 3) & (NSTAGE-1));
        else CP_COMMIT();
        CP_WAIT3();
        __syncthreads();

        uint32_t a_st = sb + st*STAGE;
        uint32_t b_st = a_st + STAGE_A;
        #pragma unroll
        for (int ks = 0; ks < 4; ks++) {
            uint32_t af[2][4], bf[2][4];
            #pragma unroll
            for (int mt = 0; mt < 2; mt++)
                ldm_x4(af[mt], a_st + (m_off + mt*16 + lr)*ROWB + ks*32 + lh);
            #pragma unroll
            for (int nt = 0; nt < 2; nt++)
                ldm_x4(bf[nt], b_st + (n_off + nt*16 + lr)*ROWB + ks*32 + lh);
            #pragma unroll
            for (int mt = 0; mt < 2; mt++) {
                #pragma unroll
                for (int n8 = 0; n8 < 4; n8++) {
                    int nt = n8 >> 1, hi = n8 & 1;
                    mma16816(acc[mt][n8], af[mt], bf[nt][hi], bf[nt][2+hi]);
                }
            }
        }
        __syncthreads();
    }

    if (EPI == 5) {
        // silu into smem (CTA owns full rows: N=128, n0=0)
        float* sred = (float*)smem;
        #pragma unroll
        for (int mt = 0; mt < 2; mt++) {
            int r0 = m_off + mt*16 + (l >> 2);
            #pragma unroll
            for (int n8 = 0; n8 < 4; n8++) {
                int cc = n_off + n8*8 + (l & 3)*2;
                #pragma unroll
                for (int q = 0; q < 4; q++) {
                    float v = acc[mt][n8][q];
                    v = v / (1.0f + __expf(-v));
                    sred[(r0 + (q>>1)*8)*128 + cc + (q&1)] = v;
                }
            }
        }
        __syncthreads();
        // LN: 4 threads per row, 32 elems each; quad shuffle reduce
        int r = tid >> 2, q4 = tid & 3;
        float vv[32];
        float s = 0.f, qs = 0.f;
        #pragma unroll 8
        for (int j = 0; j < 32; j++) {
            float v = sred[r*128 + q4*32 + j];
            vv[j] = v; s += v; qs += v*v;
        }
        s  += __shfl_xor_sync(0xffffffff, s, 1);  s  += __shfl_xor_sync(0xffffffff, s, 2);
        qs += __shfl_xor_sync(0xffffffff, qs, 1); qs += __shfl_xor_sync(0xffffffff, qs, 2);
        float mu = s * (1.0f/128.0f);
        float rs = rsqrtf(qs * (1.0f/128.0f) - mu*mu + 1e-5f);
        long row = m0 + r;
        #pragma unroll 8
        for (int j = 0; j < 32; j++) {
            int e = q4*32 + j;
            float v = (vv[j] - mu) * rs * aux[e] + aux2[e];
            __half hi, lo;
            split_h(v, hi, lo);
            outh[row*256 + e]       = hi;
            outh[row*256 + 128 + e] = lo;
        }
        return;
    }

    #pragma unroll
    for (int mt = 0; mt < 2; mt++) {
        int r0 = m0 + m_off + mt*16 + (l >> 2);
        #pragma unroll
        for (int n8 = 0; n8 < 4; n8++) {
            int cc = n0 + n_off + n8*8 + (l & 3)*2;
            float d0 = acc[mt][n8][0], d1 = acc[mt][n8][1];
            float d2 = acc[mt][n8][2], d3 = acc[mt][n8][3];
            if (EPI == 2) {
                float v0 = d0 + aux[(long)r0*128 + cc];
                float v1 = d1 + aux[(long)r0*128 + cc + 1];
                float v2 = d2 + aux[(long)(r0+8)*128 + cc];
                float v3 = d3 + aux[(long)(r0+8)*128 + cc + 1];
                outh[(long)r0*128 + cc]         = __float2half(v0);
                outh[(long)r0*128 + cc + 1]     = __float2half(v1);
                outh[(long)(r0+8)*128 + cc]     = __float2half(v2);
                outh[(long)(r0+8)*128 + cc + 1] = __float2half(v3);
            } else {
                float* p0 = Out + ((long)z*o_zstride + r0    )*ldo + cc;
                float* p1 = Out + ((long)z*o_zstride + r0 + 8)*ldo + cc;
                p0[0] = d0; p0[1] = d1;
                p1[0] = d2; p1[1] = d3;
            }
        }
    }
}

// -------------------- conv_h: 256 threads, 8 warps, 3 stages, 2 CTAs/SM --------------------
#define HSTAGE (2*STAGE_A)          // 36864
#define HNSTAGE 3
#define CONVH_SMEM (HNSTAGE*HSTAGE) // 110592

__global__ __launch_bounds__(256, 2)
void convh_mma(const __half* __restrict__ A, const __half* __restrict__ Bw,
               float* __restrict__ Out) {
    extern __shared__ char smem[];
    uint32_t sb = smem_u32(smem);
    int tid = threadIdx.x;
    int m0 = blockIdx.x * 128;
    int n0 = blockIdx.y * 128;

    int lrow  = tid >> 1;
    int lseg0 = (tid & 1) * 4;
    int p  = m0 + lrow;
    int bb = p >> 10, pix = p & 1023;
    int y = pix >> 5, x = pix & 31;

    auto load_chunk = [&](int c, int st) {
        int tap  = c >> 1;
        int koff = (c & 1) * 64;
        int ky = tap/3 - 1, kx = tap%3 - 1;
        int yy = y + ky, xx = x + kx;
        bool v = ((unsigned)yy < 32u) && ((unsigned)xx < 32u);
        const __half* asrc = v ? (A + ((long)bb*1024 + (yy<<5) + xx)*128 + koff) : A;
        uint32_t abase = sb + st*HSTAGE + lrow*ROWB;
        const __half* bsrc = Bw + (long)(n0 + lrow)*1152 + c*64;
        uint32_t bbase = sb + st*HSTAGE + STAGE_A + lrow*ROWB;
        #pragma unroll
        for (int i = 0; i < 4; i++) {
            int seg = lseg0 + i;
            cp16(abase + seg*16, asrc + seg*8, v);
            cp16(bbase + seg*16, bsrc + seg*8, true);
        }
        CP_COMMIT();
    };

    int w = tid >> 5, l = tid & 31;
    int m_off = (w >> 2) * 64;     // 0 or 64
    int n_off = (w & 3) * 32;
    int lr = l & 15, lh = (l >> 4) << 4;

    float acc[4][4][4];
    #pragma unroll
    for (int i=0;i<4;i++)
        #pragma unroll
        for (int j=0;j<4;j++)
            #pragma unroll
            for (int q=0;q<4;q++) acc[i][j][q]=0.f;

    load_chunk(0, 0);
    load_chunk(1, 1);

    for (int c = 0; c < 18; c++) {
        int st = c % HNSTAGE;
        if (c + 2 < 18) load_chunk(c + 2, (c + 2) % HNSTAGE);
        else CP_COMMIT();
        CP_WAIT2();
        __syncthreads();

        uint32_t a_st = sb + st*HSTAGE;
        uint32_t b_st = a_st + STAGE_A;
        #pragma unroll
        for (int ks = 0; ks < 4; ks++) {
            uint32_t af[4][4], bf[2][4];
            #pragma unroll
            for (int mt = 0; mt < 4; mt++)
                ldm_x4(af[mt], a_st + (m_off + mt*16 + lr)*ROWB + ks*32 + lh);
            #pragma unroll
            for (int nt = 0; nt < 2; nt++)
                ldm_x4(bf[nt], b_st + (n_off + nt*16 + lr)*ROWB + ks*32 + lh);
            #pragma unroll
            for (int mt = 0; mt < 4; mt++) {
                #pragma unroll
                for (int n8 = 0; n8 < 4; n8++) {
                    int nt = n8 >> 1, hi = n8 & 1;
                    mma16816(acc[mt][n8], af[mt], bf[nt][hi], bf[nt][2+hi]);
                }
            }
        }
        __syncthreads();
    }

    #pragma unroll
    for (int mt = 0; mt < 4; mt++) {
        int r0 = m0 + m_off + mt*16 + (l >> 2);
        #pragma unroll
        for (int n8 = 0; n8 < 4; n8++) {
            int cc = n0 + n_off + n8*8 + (l & 3)*2;
            float* p0 = Out + (long)r0*OC + cc;
            float* p1 = Out + (long)(r0+8)*OC + cc;
            p0[0] += acc[mt][n8][0]; p0[1] += acc[mt][n8][1];
            p1[0] += acc[mt][n8][2]; p1[1] += acc[mt][n8][3];
        }
    }
}

// -------------------- LSTM gates --------------------
__global__ void gates_kernel(const float* __restrict__ cc,
                             float* __restrict__ cbuf,
                             __half* __restrict__ hp,
                             float* __restrict__ out, int s, int czero) {
    int idx = blockIdx.x*blockDim.x + threadIdx.x;
    if (idx >= Pn*En) return;
    int p = idx >> 7, e = idx & 127;
    const float* row = cc + (long)p*OC;
    float ci = row[e], cf = row[128+e], co = row[256+e], cg = row[384+e];
    float si = 1.f/(1.f+__expf(-ci));
    float sf = 1.f/(1.f+__expf(-cf));
    float so = 1.f/(1.f+__expf(-co));
    float c_prev = czero ? 0.f : cbuf[idx];
    float c_next = sf*c_prev + si*tanhf(cg);
    float h_next = so*tanhf(c_next);
    cbuf[idx] = c_next;
    hp[(long)p*128 + e] = __float2half(h_next);
    int b = p >> 10, pix = p & 1023;
    out[((long)(b*16+s)*1024 + pix)*128 + e] = h_next;
}

// -------------------- launch --------------------
extern "C" void kernel_launch(void* const* d_in, const int* in_sizes, int n_in,
                              void* d_out, int out_size) {
    const float* inputs  = (const float*)d_in[0];
    const float* W_proj  = (const float*)d_in[1];
    const float* ln_g    = (const float*)d_in[2];
    const float* ln_b    = (const float*)d_in[3];
    const float* W_in    = (const float*)d_in[4];
    const float* W_out   = (const float*)d_in[5];
    const float* conv_k  = (const float*)d_in[6];
    float* out = (float*)d_out;

    float *qkv, *ccx, *cb;
    __half *xin2, *xs2, *ao, *xp, *hp, *bx, *bh, *bproj, *bqkv, *bout;
    cudaGetSymbolAddress((void**)&qkv, g_qkv);
    cudaGetSymbolAddress((void**)&ccx, g_ccx);
    cudaGetSymbolAddress((void**)&cb,  g_c);
    cudaGetSymbolAddress((void**)&xin2, g_xin2);
    cudaGetSymbolAddress((void**)&xs2, g_xs2);
    cudaGetSymbolAddress((void**)&ao,  g_ao);
    cudaGetSymbolAddress((void**)&xp,  g_xp);
    cudaGetSymbolAddress((void**)&hp,  g_hp);
    cudaGetSymbolAddress((void**)&bx,  g_bx);
    cudaGetSymbolAddress((void**)&bh,  g_bh);
    cudaGetSymbolAddress((void**)&bproj, g_bproj);
    cudaGetSymbolAddress((void**)&bqkv, g_bqkv);
    cudaGetSymbolAddress((void**)&bout, g_bout);

    cudaFuncSetAttribute(gemm_mma<1,5>, cudaFuncAttributeMaxDynamicSharedMemorySize, GEMM_SMEM);
    cudaFuncSetAttribute(gemm_mma<1,0>, cudaFuncAttributeMaxDynamicSharedMemorySize, GEMM_SMEM);
    cudaFuncSetAttribute(gemm_mma<1,2>, cudaFuncAttributeMaxDynamicSharedMemorySize, GEMM_SMEM);
    cudaFuncSetAttribute(gemm_mma<9,0>, cudaFuncAttributeMaxDynamicSharedMemorySize, GEMM_SMEM);
    cudaFuncSetAttribute(convh_mma,     cudaFuncAttributeMaxDynamicSharedMemorySize, CONVH_SMEM);

    reorder_conv<<<(int)(((long)OC*1152 + 255)/256), 256>>>(conv_k, bx, bh);
    reorder_dense<<<(640*128+255)/256, 256>>>(W_proj, W_in, W_out, bproj, bqkv, bout);
    split_in<<<(int)(((long)TOK*128+255)/256), 256>>>(inputs, xin2);

    // proj + silu + LN fused (2-term), writes xs2 [hi|lo]
    gemm_mma<1,5><<<dim3(TOK/128, 1, 1), 512, GEMM_SMEM>>>(
        xin2, bproj, nullptr, 0, ln_g, ln_b, xs2, 1024L, 0L, 0L);

    // qkv = xln @ W_in (2-term)
    gemm_mma<1,0><<<dim3(TOK/128, 3, 1), 512, GEMM_SMEM>>>(
        xs2, bqkv, qkv, 384, nullptr, nullptr, nullptr, 1024L, 0L, 0L);

    attn_core<<<Pn, 128>>>(qkv, ao);

    // xres = ao @ W_out + inputs -> 1-term fp16 xp
    gemm_mma<1,2><<<dim3(TOK/128, 1, 1), 512, GEMM_SMEM>>>(
        ao, bout, nullptr, 0, inputs, nullptr, xp, 1024L, 0L, 0L);

    // batch-parallel conv_x over all 16 steps (1-term)
    gemm_mma<9,0><<<dim3(Pn/128, 4, Sn), 512, GEMM_SMEM>>>(
        xp, bx, ccx, OC, nullptr, nullptr, nullptr, 16384L, 1024L, 8192L);

    // sequential ConvLSTM
    for (int s = 0; s < Sn; s++) {
        if (s > 0) {
            convh_mma<<<dim3(Pn/128, 4, 1), 256, CONVH_SMEM>>>(
                hp, bh, ccx + (long)s*Pn*OC);
        }
        gates_kernel<<<(Pn*En+255)/256, 256>>>(ccx + (long)s*Pn*OC, cb, hp, out, s, s == 0);
    }
}

// round 9
// speedup vs baseline: 1.6221x; 1.0235x over previous
#include <cuda_runtime.h>
#include <cuda_fp16.h>
#include <cstdint>

// Problem constants
#define Bn 8
#define Sn 16
#define En 128
#define TOK (Bn*Sn*32*32)      // 131072
#define Pn (Bn*32*32)          // 8192
#define OC 512

// -------- scratch (device globals) --------
__device__ float g_ccx[(long)TOK*OC];
__device__ float g_c[Pn*En];
__device__ __half g_qkvh[(long)TOK*384];
__device__ __half g_xin2[(long)TOK*256];
__device__ __half g_xs2[(long)TOK*256];
__device__ __half g_ao[(long)TOK*256];
__device__ __half g_xp[(long)TOK*128];
__device__ __half g_hp[Pn*128];
__device__ __half g_bx[(long)OC*1152];
__device__ __half g_bh[(long)OC*1152];
__device__ __half g_bproj[128*256];
__device__ __half g_bqkv[384*256];
__device__ __half g_bout[128*256];

// ==================== helpers ====================
__device__ __forceinline__ uint32_t smem_u32(const void* p) {
    uint32_t a;
    asm("{ .reg .u64 t; cvta.to.shared.u64 t, %1; cvt.u32.u64 %0, t; }" : "=r"(a) : "l"(p));
    return a;
}
__device__ __forceinline__ void cp16(uint32_t dst, const void* src, bool pred) {
    asm volatile("cp.async.cg.shared.global [%0], [%1], 16, %2;"
        :: "r"(dst), "l"(src), "r"(pred ? 16u : 0u));
}
#define CP_COMMIT() asm volatile("cp.async.commit_group;" ::: "memory")
#define CP_WAIT3()  asm volatile("cp.async.wait_group 3;" ::: "memory")

__device__ __forceinline__ void ldm_x4(uint32_t* r, uint32_t addr) {
    asm volatile("ldmatrix.sync.aligned.m8n8.x4.shared.b16 {%0,%1,%2,%3}, [%4];"
        : "=r"(r[0]), "=r"(r[1]), "=r"(r[2]), "=r"(r[3]) : "r"(addr));
}
__device__ __forceinline__ void mma16816(float* d, const uint32_t* a, uint32_t b0, uint32_t b1) {
    asm volatile("mma.sync.aligned.m16n8k16.row.col.f32.f16.f16.f32 "
        "{%0,%1,%2,%3}, {%4,%5,%6,%7}, {%8,%9}, {%0,%1,%2,%3};"
        : "+f"(d[0]), "+f"(d[1]), "+f"(d[2]), "+f"(d[3])
        : "r"(a[0]), "r"(a[1]), "r"(a[2]), "r"(a[3]), "r"(b0), "r"(b1));
}
__device__ __forceinline__ void split_h(float x, __half& hi, __half& lo) {
    hi = __float2half(x);
    lo = __float2half(x - __half2float(hi));
}

// -------------------- small kernels --------------------
__global__ void split_in(const float* __restrict__ inp, __half* __restrict__ x2) {
    long idx = (long)blockIdx.x*blockDim.x + threadIdx.x;
    if (idx >= (long)TOK*128) return;
    long row = idx >> 7; int e = idx & 127;
    __half hi, lo;
    split_h(inp[idx], hi, lo);
    x2[row*256 + e]       = hi;
    x2[row*256 + 128 + e] = lo;
}
__global__ void reorder_conv(const float* __restrict__ ck,
                             __half* __restrict__ bx, __half* __restrict__ bh) {
    long idx = (long)blockIdx.x*blockDim.x + threadIdx.x;
    if (idx >= (long)OC*1152) return;
    int oc = idx / 1152, k = idx % 1152;
    int tap = k >> 7, ic = k & 127;
    int ky = tap / 3, kx = tap % 3;
    bx[idx] = __float2half(ck[(((long)oc*256 + ic      )*3 + ky)*3 + kx]);
    bh[idx] = __float2half(ck[(((long)oc*256 + 128 + ic)*3 + ky)*3 + kx]);
}
__global__ void reorder_dense(const float* __restrict__ wp, const float* __restrict__ wi,
                              const float* __restrict__ wo,
                              __half* __restrict__ bp, __half* __restrict__ bi,
                              __half* __restrict__ bo) {
    int idx = blockIdx.x*blockDim.x + threadIdx.x;
    if (idx >= 640*128) return;
    int n = idx >> 7, k = idx & 127;
    const float* w; __half* b; int nn, N;
    if (n < 128)      { w = wp; b = bp; nn = n;       N = 128; }
    else if (n < 512) { w = wi; b = bi; nn = n - 128; N = 384; }
    else              { w = wo; b = bo; nn = n - 512; N = 128; }
    __half v = __float2half(w[k*N + nn]);
    b[nn*256 + k]       = v;
    b[nn*256 + 128 + k] = v;
}

// -------------------- attention core (fp16 qkv in) --------------------
__global__ __launch_bounds__(128)
void attn_core(const __half* __restrict__ qkv, __half* __restrict__ ao) {
    __shared__ float qs[16][384];
    int bid = blockIdx.x;
    int b = bid >> 10, hw = bid & 1023;
    int tid = threadIdx.x;
    for (int idx = tid; idx < 16*192; idx += 128) {
        int t = idx / 192, f = idx % 192;
        __half2 h2 = ((const __half2*)(qkv + ((long)(b*16+t)*1024 + hw)*384))[f];
        float2 f2 = __half22float2(h2);
        qs[t][2*f]   = f2.x;
        qs[t][2*f+1] = f2.y;
    }
    __syncthreads();
    int i = tid >> 4, srow = tid & 15;
    float qd[16];
    #pragma unroll
    for (int d=0; d<16; d++) qd[d] = qs[srow][i*48+d];
    float sc[16];
    float mx = -1e30f;
    #pragma unroll
    for (int l=0;l<16;l++) {
        float sv = 0.f;
        #pragma unroll
        for (int d=0;d<16;d++) sv += qd[d]*qs[l][i*48+16+d];
        sv = sv*0.25f + (l<=srow ? 1.0f : -1000.0f);
        sc[l]=sv; mx = fmaxf(mx, sv);
    }
    float sum=0.f;
    #pragma unroll
    for (int l=0;l<16;l++){ sc[l]=__expf(sc[l]-mx); sum+=sc[l]; }
    float inv = 1.0f/sum;
    float o[16];
    #pragma unroll
    for (int d=0;d<16;d++) o[d]=0.f;
    #pragma unroll
    for (int l=0;l<16;l++) {
        float wl = sc[l]*inv;
        #pragma unroll
        for (int d=0;d<16;d++) o[d] += wl*qs[l][i*48+32+d];
    }
    long t = (long)(b*16+srow)*1024 + hw;
    #pragma unroll
    for (int d=0;d<16;d++) {
        __half hi, lo;
        split_h(o[d], hi, lo);
        ao[t*256 + i*16 + d]       = hi;
        ao[t*256 + 128 + i*16 + d] = lo;
    }
}

// -------------------- universal warp-MMA fp16 GEMM / implicit conv --------------------
// CTA 128x128, 16 warps 32x32, chunks of 64, 4-stage cp.async.
// NTAP=1 dense (A rows 256): NCH chunks (4 = 2-term, 2 = 1-term hi half).
// NTAP=9 conv gather (A rows 128, NCH=18).
// EPI: 0 store f32 | 1 accumulate f32 | 2 +residual -> fp16
//      5 silu+LN+split -> fp16 [hi|lo] | 6 store fp16
#define ROWB 144
#define STAGE_A (128*ROWB)
#define STAGE   (2*STAGE_A)
#define NSTAGE  4
#define GEMM_SMEM (NSTAGE*STAGE)  // 147456

template<int NTAP, int NCH, int EPI>
__global__ __launch_bounds__(512, 1)
void gemm_mma(const __half* __restrict__ A, const __half* __restrict__ Bw,
              float* __restrict__ Out, int ldo,
              const float* __restrict__ aux, const float* __restrict__ aux2,
              __half* __restrict__ outh,
              long a_bstride, long a_zstride, long o_zstride) {
    constexpr int ALEN = (NTAP == 9) ? 128 : 256;   // row stride (halfs)
    constexpr int CPT  = ALEN / 64;
    extern __shared__ char smem[];
    uint32_t sb = smem_u32(smem);

    int tid = threadIdx.x;
    int m0 = blockIdx.x * 128;
    int n0 = blockIdx.y * 128;
    int z  = blockIdx.z;

    int lrow = tid >> 2;
    int lseg = (tid & 3) * 2;
    int p = m0 + lrow;
    int bb = p >> 10, pix = p & 1023;
    int y = pix >> 5, x = pix & 31;
    long arow_base = (long)bb * a_bstride + (long)z * a_zstride;

    auto load_chunk = [&](int c, int st) {
        int koff = (c % CPT) * 64;
        bool v = true;
        long arow;
        if (NTAP == 9) {
            int tap = c / CPT;
            int ky = tap/3 - 1, kx = tap%3 - 1;
            int yy = y + ky, xx = x + kx;
            v = ((unsigned)yy < 32u) && ((unsigned)xx < 32u);
            arow = arow_base + ((yy<<5) + xx);
        } else {
            arow = arow_base + pix;
        }
        const __half* asrc = v ? (A + arow*ALEN + koff + lseg*8) : A;
        uint32_t ab = sb + st*STAGE + lrow*ROWB + lseg*16;
        cp16(ab,      asrc,     v);
        cp16(ab + 16, asrc + 8, v);
        const __half* bsrc = Bw + (long)(n0 + lrow)*(NTAP*ALEN) + c*64 + lseg*8;
        uint32_t bbs = sb + st*STAGE + STAGE_A + lrow*ROWB + lseg*16;
        cp16(bbs,      bsrc,     true);
        cp16(bbs + 16, bsrc + 8, true);
        CP_COMMIT();
    };

    int w = tid >> 5, l = tid & 31;
    int m_off = (w >> 2) * 32;
    int n_off = (w & 3) * 32;
    int lr = l & 15, lh = (l >> 4) << 4;

    float acc[2][4][4];
    #pragma unroll
    for (int i=0;i<2;i++)
        #pragma unroll
        for (int j=0;j<4;j++)
            #pragma unroll
            for (int q=0;q<4;q++) acc[i][j][q]=0.f;

    load_chunk(0, 0);
    if (NCH > 1) load_chunk(1, 1); else CP_COMMIT();
    if (NCH > 2) load_chunk(2, 2); else CP_COMMIT();

    for (int c = 0; c < NCH; c++) {
        int st = c & (NSTAGE-1);
        if (c + 3 < NCH) load_chunk(c + 3, (c + 3) & (NSTAGE-1));
        else CP_COMMIT();
        CP_WAIT3();
        __syncthreads();

        uint32_t a_st = sb + st*STAGE;
        uint32_t b_st = a_st + STAGE_A;
        #pragma unroll
        for (int ks = 0; ks < 4; ks++) {
            uint32_t af[2][4], bf[2][4];
            #pragma unroll
            for (int mt = 0; mt < 2; mt++)
                ldm_x4(af[mt], a_st + (m_off + mt*16 + lr)*ROWB + ks*32 + lh);
            #pragma unroll
            for (int nt = 0; nt < 2; nt++)
                ldm_x4(bf[nt], b_st + (n_off + nt*16 + lr)*ROWB + ks*32 + lh);
            #pragma unroll
            for (int mt = 0; mt < 2; mt++) {
                #pragma unroll
                for (int n8 = 0; n8 < 4; n8++) {
                    int nt = n8 >> 1, hi = n8 & 1;
                    mma16816(acc[mt][n8], af[mt], bf[nt][hi], bf[nt][2+hi]);
                }
            }
        }
        __syncthreads();
    }

    if (EPI == 5) {
        // silu into smem (CTA owns full rows: N=128, n0=0)
        float* sred = (float*)smem;
        #pragma unroll
        for (int mt = 0; mt < 2; mt++) {
            int r0 = m_off + mt*16 + (l >> 2);
            #pragma unroll
            for (int n8 = 0; n8 < 4; n8++) {
                int cc = n_off + n8*8 + (l & 3)*2;
                #pragma unroll
                for (int q = 0; q < 4; q++) {
                    float v = acc[mt][n8][q];
                    v = v / (1.0f + __expf(-v));
                    sred[(r0 + (q>>1)*8)*128 + cc + (q&1)] = v;
                }
            }
        }
        __syncthreads();
        int r = tid >> 2, q4 = tid & 3;
        float vv[32];
        float s = 0.f, qs = 0.f;
        #pragma unroll 8
        for (int j = 0; j < 32; j++) {
            float v = sred[r*128 + q4*32 + j];
            vv[j] = v; s += v; qs += v*v;
        }
        s  += __shfl_xor_sync(0xffffffff, s, 1);  s  += __shfl_xor_sync(0xffffffff, s, 2);
        qs += __shfl_xor_sync(0xffffffff, qs, 1); qs += __shfl_xor_sync(0xffffffff, qs, 2);
        float mu = s * (1.0f/128.0f);
        float rs = rsqrtf(qs * (1.0f/128.0f) - mu*mu + 1e-5f);
        long row = m0 + r;
        #pragma unroll 8
        for (int j = 0; j < 32; j++) {
            int e = q4*32 + j;
            float v = (vv[j] - mu) * rs * aux[e] + aux2[e];
            __half hi, lo;
            split_h(v, hi, lo);
            outh[row*256 + e]       = hi;
            outh[row*256 + 128 + e] = lo;
        }
        return;
    }

    #pragma unroll
    for (int mt = 0; mt < 2; mt++) {
        int r0 = m0 + m_off + mt*16 + (l >> 2);
        #pragma unroll
        for (int n8 = 0; n8 < 4; n8++) {
            int cc = n0 + n_off + n8*8 + (l & 3)*2;
            float d0 = acc[mt][n8][0], d1 = acc[mt][n8][1];
            float d2 = acc[mt][n8][2], d3 = acc[mt][n8][3];
            if (EPI == 2) {
                float v0 = d0 + aux[(long)r0*128 + cc];
                float v1 = d1 + aux[(long)r0*128 + cc + 1];
                float v2 = d2 + aux[(long)(r0+8)*128 + cc];
                float v3 = d3 + aux[(long)(r0+8)*128 + cc + 1];
                outh[(long)r0*128 + cc]         = __float2half(v0);
                outh[(long)r0*128 + cc + 1]     = __float2half(v1);
                outh[(long)(r0+8)*128 + cc]     = __float2half(v2);
                outh[(long)(r0+8)*128 + cc + 1] = __float2half(v3);
            } else if (EPI == 6) {
                __half* q0 = outh + (long)r0*ldo + cc;
                __half* q1 = outh + (long)(r0+8)*ldo + cc;
                q0[0] = __float2half(d0); q0[1] = __float2half(d1);
                q1[0] = __float2half(d2); q1[1] = __float2half(d3);
            } else {
                float* p0 = Out + ((long)z*o_zstride + r0    )*ldo + cc;
                float* p1 = Out + ((long)z*o_zstride + r0 + 8)*ldo + cc;
                if (EPI == 1) { d0 += p0[0]; d1 += p0[1]; d2 += p1[0]; d3 += p1[1]; }
                p0[0] = d0; p0[1] = d1;
                p1[0] = d2; p1[1] = d3;
            }
        }
    }
}

// -------------------- LSTM gates --------------------
__global__ void gates_kernel(const float* __restrict__ cc,
                             float* __restrict__ cbuf,
                             __half* __restrict__ hp,
                             float* __restrict__ out, int s, int czero) {
    int idx = blockIdx.x*blockDim.x + threadIdx.x;
    if (idx >= Pn*En) return;
    int p = idx >> 7, e = idx & 127;
    const float* row = cc + (long)p*OC;
    float ci = row[e], cf = row[128+e], co = row[256+e], cg = row[384+e];
    float si = 1.f/(1.f+__expf(-ci));
    float sf = 1.f/(1.f+__expf(-cf));
    float so = 1.f/(1.f+__expf(-co));
    float c_prev = czero ? 0.f : cbuf[idx];
    float c_next = sf*c_prev + si*tanhf(cg);
    float h_next = so*tanhf(c_next);
    cbuf[idx] = c_next;
    hp[(long)p*128 + e] = __float2half(h_next);
    int b = p >> 10, pix = p & 1023;
    out[((long)(b*16+s)*1024 + pix)*128 + e] = h_next;
}

// -------------------- launch --------------------
extern "C" void kernel_launch(void* const* d_in, const int* in_sizes, int n_in,
                              void* d_out, int out_size) {
    const float* inputs  = (const float*)d_in[0];
    const float* W_proj  = (const float*)d_in[1];
    const float* ln_g    = (const float*)d_in[2];
    const float* ln_b    = (const float*)d_in[3];
    const float* W_in    = (const float*)d_in[4];
    const float* W_out   = (const float*)d_in[5];
    const float* conv_k  = (const float*)d_in[6];
    float* out = (float*)d_out;

    float *ccx, *cb;
    __half *qkvh, *xin2, *xs2, *ao, *xp, *hp, *bx, *bh, *bproj, *bqkv, *bout;
    cudaGetSymbolAddress((void**)&ccx, g_ccx);
    cudaGetSymbolAddress((void**)&cb,  g_c);
    cudaGetSymbolAddress((void**)&qkvh, g_qkvh);
    cudaGetSymbolAddress((void**)&xin2, g_xin2);
    cudaGetSymbolAddress((void**)&xs2, g_xs2);
    cudaGetSymbolAddress((void**)&ao,  g_ao);
    cudaGetSymbolAddress((void**)&xp,  g_xp);
    cudaGetSymbolAddress((void**)&hp,  g_hp);
    cudaGetSymbolAddress((void**)&bx,  g_bx);
    cudaGetSymbolAddress((void**)&bh,  g_bh);
    cudaGetSymbolAddress((void**)&bproj, g_bproj);
    cudaGetSymbolAddress((void**)&bqkv, g_bqkv);
    cudaGetSymbolAddress((void**)&bout, g_bout);

    cudaFuncSetAttribute((void*)gemm_mma<1,4,5>, cudaFuncAttributeMaxDynamicSharedMemorySize, GEMM_SMEM);
    cudaFuncSetAttribute((void*)gemm_mma<1,2,6>, cudaFuncAttributeMaxDynamicSharedMemorySize, GEMM_SMEM);
    cudaFuncSetAttribute((void*)gemm_mma<1,4,2>, cudaFuncAttributeMaxDynamicSharedMemorySize, GEMM_SMEM);
    cudaFuncSetAttribute((void*)gemm_mma<9,18,0>, cudaFuncAttributeMaxDynamicSharedMemorySize, GEMM_SMEM);
    cudaFuncSetAttribute((void*)gemm_mma<9,18,1>, cudaFuncAttributeMaxDynamicSharedMemorySize, GEMM_SMEM);

    reorder_conv<<<(int)(((long)OC*1152 + 255)/256), 256>>>(conv_k, bx, bh);
    reorder_dense<<<(640*128+255)/256, 256>>>(W_proj, W_in, W_out, bproj, bqkv, bout);
    split_in<<<(int)(((long)TOK*128+255)/256), 256>>>(inputs, xin2);

    // proj + silu + LN fused (2-term), writes xs2 [hi|lo]
    gemm_mma<1,4,5><<<dim3(TOK/128, 1, 1), 512, GEMM_SMEM>>>(
        xin2, bproj, nullptr, 0, ln_g, ln_b, xs2, 1024L, 0L, 0L);

    // qkv = xln @ W_in (1-term, fp16 out)
    gemm_mma<1,2,6><<<dim3(TOK/128, 3, 1), 512, GEMM_SMEM>>>(
        xs2, bqkv, nullptr, 384, nullptr, nullptr, qkvh, 1024L, 0L, 0L);

    attn_core<<<Pn, 128>>>(qkvh, ao);

    // xres = ao @ W_out + inputs -> 1-term fp16 xp
    gemm_mma<1,4,2><<<dim3(TOK/128, 1, 1), 512, GEMM_SMEM>>>(
        ao, bout, nullptr, 0, inputs, nullptr, xp, 1024L, 0L, 0L);

    // batch-parallel conv_x over all 16 steps (1-term)
    gemm_mma<9,18,0><<<dim3(Pn/128, 4, Sn), 512, GEMM_SMEM>>>(
        xp, bx, ccx, OC, nullptr, nullptr, nullptr, 16384L, 1024L, 8192L);

    // sequential ConvLSTM
    for (int s = 0; s < Sn; s++) {
        if (s > 0) {
            gemm_mma<9,18,1><<<dim3(Pn/128, 4, 1), 512, GEMM_SMEM>>>(
                hp, bh, ccx + (long)s*Pn*OC, OC, nullptr, nullptr, nullptr, 1024L, 0L, 0L);
        }
        gates_kernel<<<(Pn*En+255)/256, 256>>>(ccx + (long)s*Pn*OC, cb, hp, out, s, s == 0);
    }
}

// round 10
// speedup vs baseline: 1.7801x; 1.0974x over previous
#include <cuda_runtime.h>
#include <cuda_fp16.h>
#include <cstdint>

// Problem constants
#define Bn 8
#define Sn 16
#define En 128
#define TOK (Bn*Sn*32*32)      // 131072
#define Pn (Bn*32*32)          // 8192
#define OC 512

// -------- scratch (device globals) --------
__device__ float g_ccx[(long)TOK*OC];
__device__ float g_c[Pn*En];
__device__ __half g_qkvh[(long)TOK*384];
__device__ __half g_xin2[(long)TOK*256];
__device__ __half g_xs2[(long)TOK*256];
__device__ __half g_ao[(long)TOK*256];
__device__ __half g_xp[(long)TOK*128];
__device__ __half g_hp[Pn*128];
__device__ __half g_bx[(long)OC*1152];
__device__ __half g_bh[(long)OC*1152];
__device__ __half g_bproj[128*256];
__device__ __half g_bqkv[384*256];
__device__ __half g_bout[128*256];

// ==================== helpers ====================
__device__ __forceinline__ uint32_t smem_u32(const void* p) {
    uint32_t a;
    asm("{ .reg .u64 t; cvta.to.shared.u64 t, %1; cvt.u32.u64 %0, t; }" : "=r"(a) : "l"(p));
    return a;
}
__device__ __forceinline__ void cp16(uint32_t dst, const void* src, bool pred) {
    asm volatile("cp.async.cg.shared.global [%0], [%1], 16, %2;"
        :: "r"(dst), "l"(src), "r"(pred ? 16u : 0u));
}
#define CP_COMMIT() asm volatile("cp.async.commit_group;" ::: "memory")
#define CP_WAIT3()  asm volatile("cp.async.wait_group 3;" ::: "memory")

__device__ __forceinline__ void ldm_x4(uint32_t* r, uint32_t addr) {
    asm volatile("ldmatrix.sync.aligned.m8n8.x4.shared.b16 {%0,%1,%2,%3}, [%4];"
        : "=r"(r[0]), "=r"(r[1]), "=r"(r[2]), "=r"(r[3]) : "r"(addr));
}
__device__ __forceinline__ void mma16816(float* d, const uint32_t* a, uint32_t b0, uint32_t b1) {
    asm volatile("mma.sync.aligned.m16n8k16.row.col.f32.f16.f16.f32 "
        "{%0,%1,%2,%3}, {%4,%5,%6,%7}, {%8,%9}, {%0,%1,%2,%3};"
        : "+f"(d[0]), "+f"(d[1]), "+f"(d[2]), "+f"(d[3])
        : "r"(a[0]), "r"(a[1]), "r"(a[2]), "r"(a[3]), "r"(b0), "r"(b1));
}
__device__ __forceinline__ void split_h(float x, __half& hi, __half& lo) {
    hi = __float2half(x);
    lo = __float2half(x - __half2float(hi));
}

// -------------------- small kernels --------------------
// vectorized: float2 in, half2 out (coalesced 4B stores)
__global__ void split_in(const float* __restrict__ inp, __half* __restrict__ x2) {
    long idx = (long)blockIdx.x*blockDim.x + threadIdx.x;
    if (idx >= (long)TOK*64) return;
    long row = idx >> 6; int e2 = idx & 63;
    float2 v = ((const float2*)inp)[idx];
    __half h0, l0, h1, l1;
    split_h(v.x, h0, l0);
    split_h(v.y, h1, l1);
    ((__half2*)(x2 + row*256))[e2]      = __halves2half2(h0, h1);
    ((__half2*)(x2 + row*256 + 128))[e2] = __halves2half2(l0, l1);
}
__global__ void reorder_conv(const float* __restrict__ ck,
                             __half* __restrict__ bx, __half* __restrict__ bh) {
    long idx = (long)blockIdx.x*blockDim.x + threadIdx.x;
    if (idx >= (long)OC*1152) return;
    int oc = idx / 1152, k = idx % 1152;
    int tap = k >> 7, ic = k & 127;
    int ky = tap / 3, kx = tap % 3;
    bx[idx] = __float2half(ck[(((long)oc*256 + ic      )*3 + ky)*3 + kx]);
    bh[idx] = __float2half(ck[(((long)oc*256 + 128 + ic)*3 + ky)*3 + kx]);
}
__global__ void reorder_dense(const float* __restrict__ wp, const float* __restrict__ wi,
                              const float* __restrict__ wo,
                              __half* __restrict__ bp, __half* __restrict__ bi,
                              __half* __restrict__ bo) {
    int idx = blockIdx.x*blockDim.x + threadIdx.x;
    if (idx >= 640*128) return;
    int n = idx >> 7, k = idx & 127;
    const float* w; __half* b; int nn, N;
    if (n < 128)      { w = wp; b = bp; nn = n;       N = 128; }
    else if (n < 512) { w = wi; b = bi; nn = n - 128; N = 384; }
    else              { w = wo; b = bo; nn = n - 512; N = 128; }
    __half v = __float2half(w[k*N + nn]);
    b[nn*256 + k]       = v;
    b[nn*256 + 128 + k] = v;
}

// -------------------- attention core (fp16 qkv in) --------------------
__global__ __launch_bounds__(128)
void attn_core(const __half* __restrict__ qkv, __half* __restrict__ ao) {
    __shared__ float qs[16][384];
    int bid = blockIdx.x;
    int b = bid >> 10, hw = bid & 1023;
    int tid = threadIdx.x;
    for (int idx = tid; idx < 16*192; idx += 128) {
        int t = idx / 192, f = idx % 192;
        __half2 h2 = ((const __half2*)(qkv + ((long)(b*16+t)*1024 + hw)*384))[f];
        float2 f2 = __half22float2(h2);
        qs[t][2*f]   = f2.x;
        qs[t][2*f+1] = f2.y;
    }
    __syncthreads();
    int i = tid >> 4, srow = tid & 15;
    float qd[16];
    #pragma unroll
    for (int d=0; d<16; d++) qd[d] = qs[srow][i*48+d];
    float sc[16];
    float mx = -1e30f;
    #pragma unroll
    for (int l=0;l<16;l++) {
        float sv = 0.f;
        #pragma unroll
        for (int d=0;d<16;d++) sv += qd[d]*qs[l][i*48+16+d];
        sv = sv*0.25f + (l<=srow ? 1.0f : -1000.0f);
        sc[l]=sv; mx = fmaxf(mx, sv);
    }
    float sum=0.f;
    #pragma unroll
    for (int l=0;l<16;l++){ sc[l]=__expf(sc[l]-mx); sum+=sc[l]; }
    float inv = 1.0f/sum;
    float o[16];
    #pragma unroll
    for (int d=0;d<16;d++) o[d]=0.f;
    #pragma unroll
    for (int l=0;l<16;l++) {
        float wl = sc[l]*inv;
        #pragma unroll
        for (int d=0;d<16;d++) o[d] += wl*qs[l][i*48+32+d];
    }
    long t = (long)(b*16+srow)*1024 + hw;
    #pragma unroll
    for (int d=0;d<16;d++) {
        __half hi, lo;
        split_h(o[d], hi, lo);
        ao[t*256 + i*16 + d]       = hi;
        ao[t*256 + 128 + i*16 + d] = lo;
    }
}

// -------------------- universal warp-MMA fp16 GEMM / implicit conv --------------------
// CTA 128x128, 16 warps 32x32, chunks of 64, 4-stage cp.async.
// NTAP=1 dense (A rows 256): NCH chunks (4 = 2-term, 2 = 1-term hi half).
// NTAP=9 conv gather (A rows 128, NCH=18).
// EPI: 0 store f32 | 1 accumulate f32 | 2 +residual -> fp16
//      5 silu+LN+split -> fp16 [hi|lo] | 6 store fp16
#define ROWB 144
#define STAGE_A (128*ROWB)
#define STAGE   (2*STAGE_A)
#define NSTAGE  4
#define GEMM_SMEM (NSTAGE*STAGE)  // 147456
#define SREDW 132                 // padded f32 row stride for LN epilogue

template<int NTAP, int NCH, int EPI>
__global__ __launch_bounds__(512, 1)
void gemm_mma(const __half* __restrict__ A, const __half* __restrict__ Bw,
              float* __restrict__ Out, int ldo,
              const float* __restrict__ aux, const float* __restrict__ aux2,
              __half* __restrict__ outh,
              long a_bstride, long a_zstride, long o_zstride) {
    constexpr int ALEN = (NTAP == 9) ? 128 : 256;   // row stride (halfs)
    constexpr int CPT  = ALEN / 64;
    extern __shared__ char smem[];
    uint32_t sb = smem_u32(smem);

    int tid = threadIdx.x;
    int m0 = blockIdx.x * 128;
    int n0 = blockIdx.y * 128;
    int z  = blockIdx.z;

    int lrow = tid >> 2;
    int lseg = (tid & 3) * 2;
    int p = m0 + lrow;
    int bb = p >> 10, pix = p & 1023;
    int y = pix >> 5, x = pix & 31;
    long arow_base = (long)bb * a_bstride + (long)z * a_zstride;

    auto load_chunk = [&](int c, int st) {
        int koff = (c % CPT) * 64;
        bool v = true;
        long arow;
        if (NTAP == 9) {
            int tap = c / CPT;
            int ky = tap/3 - 1, kx = tap%3 - 1;
            int yy = y + ky, xx = x + kx;
            v = ((unsigned)yy < 32u) && ((unsigned)xx < 32u);
            arow = arow_base + ((yy<<5) + xx);
        } else {
            arow = arow_base + pix;
        }
        const __half* asrc = v ? (A + arow*ALEN + koff + lseg*8) : A;
        uint32_t ab = sb + st*STAGE + lrow*ROWB + lseg*16;
        cp16(ab,      asrc,     v);
        cp16(ab + 16, asrc + 8, v);
        const __half* bsrc = Bw + (long)(n0 + lrow)*(NTAP*ALEN) + c*64 + lseg*8;
        uint32_t bbs = sb + st*STAGE + STAGE_A + lrow*ROWB + lseg*16;
        cp16(bbs,      bsrc,     true);
        cp16(bbs + 16, bsrc + 8, true);
        CP_COMMIT();
    };

    int w = tid >> 5, l = tid & 31;
    int m_off = (w >> 2) * 32;
    int n_off = (w & 3) * 32;
    int lr = l & 15, lh = (l >> 4) << 4;

    float acc[2][4][4];
    #pragma unroll
    for (int i=0;i<2;i++)
        #pragma unroll
        for (int j=0;j<4;j++)
            #pragma unroll
            for (int q=0;q<4;q++) acc[i][j][q]=0.f;

    load_chunk(0, 0);
    if (NCH > 1) load_chunk(1, 1); else CP_COMMIT();
    if (NCH > 2) load_chunk(2, 2); else CP_COMMIT();

    for (int c = 0; c < NCH; c++) {
        int st = c & (NSTAGE-1);
        if (c + 3 < NCH) load_chunk(c + 3, (c + 3) & (NSTAGE-1));
        else CP_COMMIT();
        CP_WAIT3();
        __syncthreads();

        uint32_t a_st = sb + st*STAGE;
        uint32_t b_st = a_st + STAGE_A;
        #pragma unroll
        for (int ks = 0; ks < 4; ks++) {
            uint32_t af[2][4], bf[2][4];
            #pragma unroll
            for (int mt = 0; mt < 2; mt++)
                ldm_x4(af[mt], a_st + (m_off + mt*16 + lr)*ROWB + ks*32 + lh);
            #pragma unroll
            for (int nt = 0; nt < 2; nt++)
                ldm_x4(bf[nt], b_st + (n_off + nt*16 + lr)*ROWB + ks*32 + lh);
            #pragma unroll
            for (int mt = 0; mt < 2; mt++) {
                #pragma unroll
                for (int n8 = 0; n8 < 4; n8++) {
                    int nt = n8 >> 1, hi = n8 & 1;
                    mma16816(acc[mt][n8], af[mt], bf[nt][hi], bf[nt][2+hi]);
                }
            }
        }
        __syncthreads();
    }

    if (EPI == 5) {
        // silu into padded smem (CTA owns full rows: N=128, n0=0)
        float* sred = (float*)smem;
        #pragma unroll
        for (int mt = 0; mt < 2; mt++) {
            int r0 = m_off + mt*16 + (l >> 2);
            #pragma unroll
            for (int n8 = 0; n8 < 4; n8++) {
                int cc = n_off + n8*8 + (l & 3)*2;
                #pragma unroll
                for (int q = 0; q < 4; q++) {
                    float v = acc[mt][n8][q];
                    v = v / (1.0f + __expf(-v));
                    sred[(r0 + (q>>1)*8)*SREDW + cc + (q&1)] = v;
                }
            }
        }
        __syncthreads();
        // LN: warp-per-row (8 rows/warp), conflict-free strided reads
        #pragma unroll
        for (int rr = 0; rr < 8; rr++) {
            int row = w*8 + rr;
            float v4[4];
            float s = 0.f, qs = 0.f;
            #pragma unroll
            for (int j = 0; j < 4; j++) {
                float v = sred[row*SREDW + l + j*32];
                v4[j] = v; s += v; qs += v*v;
            }
            #pragma unroll
            for (int off = 16; off; off >>= 1) {
                s  += __shfl_xor_sync(0xffffffff, s, off);
                qs += __shfl_xor_sync(0xffffffff, qs, off);
            }
            float mu = s * (1.0f/128.0f);
            float rs = rsqrtf(qs * (1.0f/128.0f) - mu*mu + 1e-5f);
            long grow = m0 + row;
            #pragma unroll
            for (int j = 0; j < 4; j++) {
                int e = l + j*32;
                float v = (v4[j] - mu) * rs * aux[e] + aux2[e];
                __half hi, lo;
                split_h(v, hi, lo);
                outh[grow*256 + e]       = hi;
                outh[grow*256 + 128 + e] = lo;
            }
        }
        return;
    }

    #pragma unroll
    for (int mt = 0; mt < 2; mt++) {
        int r0 = m0 + m_off + mt*16 + (l >> 2);
        #pragma unroll
        for (int n8 = 0; n8 < 4; n8++) {
            int cc = n0 + n_off + n8*8 + (l & 3)*2;
            float d0 = acc[mt][n8][0], d1 = acc[mt][n8][1];
            float d2 = acc[mt][n8][2], d3 = acc[mt][n8][3];
            if (EPI == 2) {
                float v0 = d0 + aux[(long)r0*128 + cc];
                float v1 = d1 + aux[(long)r0*128 + cc + 1];
                float v2 = d2 + aux[(long)(r0+8)*128 + cc];
                float v3 = d3 + aux[(long)(r0+8)*128 + cc + 1];
                outh[(long)r0*128 + cc]         = __float2half(v0);
                outh[(long)r0*128 + cc + 1]     = __float2half(v1);
                outh[(long)(r0+8)*128 + cc]     = __float2half(v2);
                outh[(long)(r0+8)*128 + cc + 1] = __float2half(v3);
            } else if (EPI == 6) {
                __half* q0 = outh + (long)r0*ldo + cc;
                __half* q1 = outh + (long)(r0+8)*ldo + cc;
                q0[0] = __float2half(d0); q0[1] = __float2half(d1);
                q1[0] = __float2half(d2); q1[1] = __float2half(d3);
            } else {
                float* p0 = Out + ((long)z*o_zstride + r0    )*ldo + cc;
                float* p1 = Out + ((long)z*o_zstride + r0 + 8)*ldo + cc;
                if (EPI == 1) { d0 += p0[0]; d1 += p0[1]; d2 += p1[0]; d3 += p1[1]; }
                p0[0] = d0; p0[1] = d1;
                p1[0] = d2; p1[1] = d3;
            }
        }
    }
}

// -------------------- LSTM gates --------------------
__global__ void gates_kernel(const float* __restrict__ cc,
                             float* __restrict__ cbuf,
                             __half* __restrict__ hp,
                             float* __restrict__ out, int s, int czero) {
    int idx = blockIdx.x*blockDim.x + threadIdx.x;
    if (idx >= Pn*En) return;
    int p = idx >> 7, e = idx & 127;
    const float* row = cc + (long)p*OC;
    float ci = row[e], cf = row[128+e], co = row[256+e], cg = row[384+e];
    float si = 1.f/(1.f+__expf(-ci));
    float sf = 1.f/(1.f+__expf(-cf));
    float so = 1.f/(1.f+__expf(-co));
    float c_prev = czero ? 0.f : cbuf[idx];
    float c_next = sf*c_prev + si*tanhf(cg);
    float h_next = so*tanhf(c_next);
    cbuf[idx] = c_next;
    hp[(long)p*128 + e] = __float2half(h_next);
    int b = p >> 10, pix = p & 1023;
    out[((long)(b*16+s)*1024 + pix)*128 + e] = h_next;
}

// -------------------- launch --------------------
extern "C" void kernel_launch(void* const* d_in, const int* in_sizes, int n_in,
                              void* d_out, int out_size) {
    const float* inputs  = (const float*)d_in[0];
    const float* W_proj  = (const float*)d_in[1];
    const float* ln_g    = (const float*)d_in[2];
    const float* ln_b    = (const float*)d_in[3];
    const float* W_in    = (const float*)d_in[4];
    const float* W_out   = (const float*)d_in[5];
    const float* conv_k  = (const float*)d_in[6];
    float* out = (float*)d_out;

    float *ccx, *cb;
    __half *qkvh, *xin2, *xs2, *ao, *xp, *hp, *bx, *bh, *bproj, *bqkv, *bout;
    cudaGetSymbolAddress((void**)&ccx, g_ccx);
    cudaGetSymbolAddress((void**)&cb,  g_c);
    cudaGetSymbolAddress((void**)&qkvh, g_qkvh);
    cudaGetSymbolAddress((void**)&xin2, g_xin2);
    cudaGetSymbolAddress((void**)&xs2, g_xs2);
    cudaGetSymbolAddress((void**)&ao,  g_ao);
    cudaGetSymbolAddress((void**)&xp,  g_xp);
    cudaGetSymbolAddress((void**)&hp,  g_hp);
    cudaGetSymbolAddress((void**)&bx,  g_bx);
    cudaGetSymbolAddress((void**)&bh,  g_bh);
    cudaGetSymbolAddress((void**)&bproj, g_bproj);
    cudaGetSymbolAddress((void**)&bqkv, g_bqkv);
    cudaGetSymbolAddress((void**)&bout, g_bout);

    cudaFuncSetAttribute((void*)gemm_mma<1,4,5>, cudaFuncAttributeMaxDynamicSharedMemorySize, GEMM_SMEM);
    cudaFuncSetAttribute((void*)gemm_mma<1,2,6>, cudaFuncAttributeMaxDynamicSharedMemorySize, GEMM_SMEM);
    cudaFuncSetAttribute((void*)gemm_mma<1,4,2>, cudaFuncAttributeMaxDynamicSharedMemorySize, GEMM_SMEM);
    cudaFuncSetAttribute((void*)gemm_mma<9,18,0>, cudaFuncAttributeMaxDynamicSharedMemorySize, GEMM_SMEM);
    cudaFuncSetAttribute((void*)gemm_mma<9,18,1>, cudaFuncAttributeMaxDynamicSharedMemorySize, GEMM_SMEM);

    reorder_conv<<<(int)(((long)OC*1152 + 255)/256), 256>>>(conv_k, bx, bh);
    reorder_dense<<<(640*128+255)/256, 256>>>(W_proj, W_in, W_out, bproj, bqkv, bout);
    split_in<<<(int)(((long)TOK*64+255)/256), 256>>>(inputs, xin2);

    // proj + silu + LN fused (2-term), writes xs2 [hi|lo]
    gemm_mma<1,4,5><<<dim3(TOK/128, 1, 1), 512, GEMM_SMEM>>>(
        xin2, bproj, nullptr, 0, ln_g, ln_b, xs2, 1024L, 0L, 0L);

    // qkv = xln @ W_in (1-term, fp16 out)
    gemm_mma<1,2,6><<<dim3(TOK/128, 3, 1), 512, GEMM_SMEM>>>(
        xs2, bqkv, nullptr, 384, nullptr, nullptr, qkvh, 1024L, 0L, 0L);

    attn_core<<<Pn, 128>>>(qkvh, ao);

    // xres = ao @ W_out + inputs -> 1-term fp16 xp
    gemm_mma<1,4,2><<<dim3(TOK/128, 1, 1), 512, GEMM_SMEM>>>(
        ao, bout, nullptr, 0, inputs, nullptr, xp, 1024L, 0L, 0L);

    // batch-parallel conv_x over all 16 steps (1-term)
    gemm_mma<9,18,0><<<dim3(Pn/128, 4, Sn), 512, GEMM_SMEM>>>(
        xp, bx, ccx, OC, nullptr, nullptr, nullptr, 16384L, 1024L, 8192L);

    // sequential ConvLSTM
    for (int s = 0; s < Sn; s++) {
        if (s > 0) {
            gemm_mma<9,18,1><<<dim3(Pn/128, 4, 1), 512, GEMM_SMEM>>>(
                hp, bh, ccx + (long)s*Pn*OC, OC, nullptr, nullptr, nullptr, 1024L, 0L, 0L);
        }
        gates_kernel<<<(Pn*En+255)/256, 256>>>(ccx + (long)s*Pn*OC, cb, hp, out, s, s == 0);
    }
}